// round 5
// baseline (speedup 1.0000x reference)
#include <cuda_runtime.h>
#include <cstdint>

// Problem constants
#define SQ 1024
#define HD 768
#define NH 12
#define DH 64
#define NB 8
#define BHCOUNT (NB*NH)   // 96
#define MROWS (NB*SQ)     // 8192

// Scratch (device globals; tf32 bit patterns stored as float)
__device__ float g_q[BHCOUNT*SQ*DH];    // dperm'd tf32
__device__ float g_k[BHCOUNT*SQ*DH];    // dperm'd tf32
__device__ float g_v[BHCOUNT*SQ*DH];    // natural tf32
__device__ float g_ao[MROWS*HD];        // kperm'd tf32
__device__ float g_ht[MROWS*HD];        // kperm'd tf32 input h
__device__ float g_wt4[4*HD*HD];        // tf32 weights (natural)

// ---------------------------------------------------------------------------
// helpers
// ---------------------------------------------------------------------------
__device__ __forceinline__ uint32_t f2tf(float x) {
    uint32_t r;
    asm("cvt.rna.tf32.f32 %0, %1;" : "=r"(r) : "f"(x));
    return r;
}
__device__ __forceinline__ float f2tff(float x) { return __uint_as_float(f2tf(x)); }
__device__ __forceinline__ int slotf(int c) { return 2*(c&3) + ((c&4)>>2); }

__device__ __forceinline__ void mma8(float* c,
                                     uint32_t a0, uint32_t a1, uint32_t a2, uint32_t a3,
                                     uint32_t b0, uint32_t b1) {
    asm volatile(
        "mma.sync.aligned.m16n8k8.row.col.f32.tf32.tf32.f32 "
        "{%0,%1,%2,%3}, {%4,%5,%6,%7}, {%8,%9}, {%0,%1,%2,%3};"
        : "+f"(c[0]), "+f"(c[1]), "+f"(c[2]), "+f"(c[3])
        : "r"(a0), "r"(a1), "r"(a2), "r"(a3), "r"(b0), "r"(b1));
}

__device__ __forceinline__ uint32_t smem_u32(const void* p) {
    uint32_t a;
    asm("{ .reg .u64 t; cvta.to.shared.u64 t, %1; cvt.u32.u64 %0, t; }"
        : "=r"(a) : "l"(p));
    return a;
}
__device__ __forceinline__ void cpa16(uint32_t dst, const void* src) {
    asm volatile("cp.async.cg.shared.global [%0], [%1], 16;" :: "r"(dst), "l"(src));
}
#define CP_COMMIT() asm volatile("cp.async.commit_group;" ::: "memory")
#define CP_WAIT0()  asm volatile("cp.async.wait_group 0;" ::: "memory")
#define CP_WAIT1()  asm volatile("cp.async.wait_group 1;" ::: "memory")

// ---------------------------------------------------------------------------
// prep: pre-round h (with k-perm) and the 4 weights (natural) to tf32
// ---------------------------------------------------------------------------
__global__ void prep(const float* __restrict__ h,
                     const float* __restrict__ wq, const float* __restrict__ wk,
                     const float* __restrict__ wv, const float* __restrict__ wo)
{
    int i = blockIdx.x * 256 + threadIdx.x;
    if (i < MROWS*HD) {
        int k = i & 7;  // HD multiple of 8, row base preserved
        g_ht[i - k + slotf(k)] = f2tff(h[i]);
    }
    if (i < 4*HD*HD) {
        int z = i / (HD*HD), r = i - z*(HD*HD);
        const float* w = (z == 0) ? wq : (z == 1 ? wk : (z == 2 ? wv : wo));
        g_wt4[i] = f2tff(w[r]);
    }
}

// ---------------------------------------------------------------------------
// tf32 GEMM via mma.sync, cp.async double-buffered, 2 CTAs/SM.
// A (kperm'd tf32) x W (rows sigma-remapped at cp.async dst) + bias.
// mode 1: QKV fused (z = blockIdx.z): z<2 -> dperm'd head-major out (g_q/g_k),
//         z==2 -> natural head-major (g_v); all pre-rounded tf32.
// mode 0: A=g_ao, C=Cout fp32 row-major.
// ---------------------------------------------------------------------------
#define GA 40
#define GB 132
#define A_ST (128*GA)
#define B_ST (32*GB)
#define STAGE (A_ST + B_ST)       // 9344 floats
#define NCHUNK (HD/32)            // 24
#define GEMM_SMEM (2*STAGE*4)     // 74752 bytes

__global__ __launch_bounds__(256, 2) void gemm_tc(
    const float* __restrict__ bias0, const float* __restrict__ bias1,
    const float* __restrict__ bias2, float* __restrict__ Cout, int mode)
{
    extern __shared__ float sm[];
    const uint32_t sb = smem_u32(sm);
    const int tid = threadIdx.x;
    const int wid = tid >> 5, lane = tid & 31;
    const int wm = wid >> 2, wn = wid & 3;
    const int g = lane >> 2, t = lane & 3;
    const int z = (mode == 1) ? blockIdx.z : 0;

    const float* A = (mode == 0) ? g_ao : g_ht;
    const float* W = g_wt4 + (size_t)((mode == 0) ? 3 : z) * HD * HD;
    const float* bias = (z == 0) ? bias0 : (z == 1 ? bias1 : bias2);
    float* C = (mode == 0) ? Cout : (z == 0 ? g_q : (z == 1 ? g_k : g_v));

    const int m0 = blockIdx.y * 128;
    const int n0 = blockIdx.x * 128;

    float acc[4][4][4];
#pragma unroll
    for (int i = 0; i < 4; ++i)
#pragma unroll
        for (int j = 0; j < 4; ++j)
#pragma unroll
            for (int r = 0; r < 4; ++r) acc[i][j][r] = 0.0f;

#define G_LOAD(cc, st) do { \
    int k0 = (cc) * 32; \
    uint32_t abase = sb + (uint32_t)((st) * STAGE) * 4; \
    uint32_t bbase = abase + A_ST * 4; \
    _Pragma("unroll") \
    for (int it = 0; it < 4; ++it) { \
        int idx = tid + it * 256; \
        int ar = idx >> 3, ac = idx & 7; \
        cpa16(abase + (uint32_t)(ar * GA + ac * 4) * 4, \
              A + (size_t)(m0 + ar) * HD + k0 + ac * 4); \
        int br = idx >> 5, bc = idx & 31; \
        int sr = (br & ~7) | slotf(br & 7); \
        cpa16(bbase + (uint32_t)(sr * GB + bc * 4) * 4, \
              W + (size_t)(k0 + br) * HD + n0 + bc * 4); \
    } \
    CP_COMMIT(); \
} while (0)

    G_LOAD(0, 0);

    for (int c = 0; c < NCHUNK; ++c) {
        const int s = c & 1;
        if (c + 1 < NCHUNK) { G_LOAD(c + 1, s ^ 1); CP_WAIT1(); }
        else CP_WAIT0();
        __syncthreads();

        const float* As = sm + s * STAGE;
        const float* Bs = As + A_ST;
#pragma unroll
        for (int ks = 0; ks < 4; ++ks) {
            float2 ap[4][2];
#pragma unroll
            for (int mf = 0; mf < 4; ++mf) {
                const float* p = As + (wm * 64 + mf * 16 + g) * GA + ks * 8 + 2 * t;
                ap[mf][0] = *(const float2*)p;
                ap[mf][1] = *(const float2*)(p + 8 * GA);
            }
            float bf[4][2];
#pragma unroll
            for (int nf = 0; nf < 4; ++nf) {
                const float* p = Bs + (ks * 8 + 2 * t) * GB + wn * 32 + nf * 8 + g;
                bf[nf][0] = p[0];
                bf[nf][1] = p[GB];
            }
#pragma unroll
            for (int mf = 0; mf < 4; ++mf)
#pragma unroll
                for (int nf = 0; nf < 4; ++nf)
                    mma8(acc[mf][nf],
                         __float_as_uint(ap[mf][0].x), __float_as_uint(ap[mf][1].x),
                         __float_as_uint(ap[mf][0].y), __float_as_uint(ap[mf][1].y),
                         __float_as_uint(bf[nf][0]), __float_as_uint(bf[nf][1]));
        }
        __syncthreads();
    }

    // epilogue
#pragma unroll
    for (int mf = 0; mf < 4; ++mf) {
#pragma unroll
        for (int nf = 0; nf < 4; ++nf) {
            int r0 = m0 + wm * 64 + mf * 16 + g;
            int ncol0 = n0 + wn * 32 + nf * 8 + 2 * t;
            int ncol1 = ncol0 + 1;
            float bb0 = bias[ncol0], bb1 = bias[ncol1];
            float v00 = acc[mf][nf][0] + bb0, v01 = acc[mf][nf][1] + bb1;
            float v10 = acc[mf][nf][2] + bb0, v11 = acc[mf][nf][3] + bb1;
            if (mode == 0) {
                *(float2*)&C[(size_t)r0 * HD + ncol0] = make_float2(v00, v01);
                *(float2*)&C[(size_t)(r0 + 8) * HD + ncol0] = make_float2(v10, v11);
            } else {
                int b = r0 >> 10, sidx = r0 & 1023;
                if (z < 2) {
                    int pc0 = (ncol0 & ~7) | slotf(ncol0 & 7);
                    int pc1 = (ncol1 & ~7) | slotf(ncol1 & 7);
                    int hh = pc0 >> 6;
                    size_t base = ((size_t)(b * NH + hh) * SQ + sidx) * DH;
                    C[base + (pc0 & 63)] = f2tff(v00);
                    C[base + (pc1 & 63)] = f2tff(v01);
                    C[base + 8 * DH + (pc0 & 63)] = f2tff(v10);
                    C[base + 8 * DH + (pc1 & 63)] = f2tff(v11);
                } else {
                    int hh = ncol0 >> 6, dd = ncol0 & 63;
                    size_t base = ((size_t)(b * NH + hh) * SQ + sidx) * DH + dd;
                    *(float2*)&C[base] = make_float2(f2tff(v00), f2tff(v01));
                    *(float2*)&C[base + 8 * DH] = make_float2(f2tff(v10), f2tff(v11));
                }
            }
        }
    }
}

// ---------------------------------------------------------------------------
// Flash attention: 512 threads (16 warps), 256 q-rows/CTA, Q resident in smem,
// K/V cp.async double-buffered, LDS.64 fragment feeds via perm layouts.
// smem floats: Q[256][72], K[2][64][72], V[2][64][68] (rows sigma-permuted),
//              P[256][72] (cols sigma-permuted).
// ---------------------------------------------------------------------------
#define QSTR 72
#define KSTR 72
#define VSTR 68
#define PSTR 72
#define Q_OFF 0
#define K_OFF(s) (256*QSTR + (s)*64*KSTR)
#define V_OFF(s) (256*QSTR + 2*64*KSTR + (s)*64*VSTR)
#define P_OFF    (256*QSTR + 2*64*KSTR + 2*64*VSTR)
#define ATTN_SMEM ((P_OFF + 256*PSTR) * 4)   // 219136 bytes

__global__ __launch_bounds__(512) void attn_kernel(
    const float* __restrict__ bias, const int* __restrict__ mask)
{
    extern __shared__ float sm[];
    const uint32_t sb = smem_u32(sm);
    const float FINF = __int_as_float(0x7f800000);

    const int bh = blockIdx.x;
    const int b = bh / NH, hh = bh - b * NH;
    const int q0 = blockIdx.y * 256;
    const int tid = threadIdx.x;
    const int wid = tid >> 5, lane = tid & 31;
    const int g = lane >> 2, t = lane & 3;
    const int rl = wid * 16 + g;

    const float* qg = g_q + ((size_t)bh * SQ + q0) * DH;
    const float* kg = g_k + (size_t)bh * SQ * DH;
    const float* vg = g_v + (size_t)bh * SQ * DH;

    // prologue: Q tile + chunk0 K/V, one group
#pragma unroll
    for (int it = 0; it < 8; ++it) {
        int idx = tid + it * 512;
        int row = idx >> 4, c4 = idx & 15;
        cpa16(sb + (uint32_t)(Q_OFF + row * QSTR + c4 * 4) * 4,
              qg + (size_t)row * 64 + c4 * 4);
    }
#pragma unroll
    for (int it = 0; it < 2; ++it) {
        int idx = tid + it * 512;
        int row = idx >> 4, c4 = idx & 15;
        cpa16(sb + (uint32_t)(K_OFF(0) + row * KSTR + c4 * 4) * 4,
              kg + (size_t)row * 64 + c4 * 4);
        int vr = (row & ~7) | slotf(row & 7);
        cpa16(sb + (uint32_t)(V_OFF(0) + vr * VSTR + c4 * 4) * 4,
              vg + (size_t)row * 64 + c4 * 4);
    }
    CP_COMMIT();

    const int r0 = q0 + rl, r1 = r0 + 8;
    const float* bias_r0 = bias + ((size_t)(b * SQ + r0) * SQ) * NH + hh;
    const float* bias_r1 = bias + ((size_t)(b * SQ + r1) * SQ) * NH + hh;
    const int* mask_r0 = mask + (size_t)(b * SQ + r0) * SQ;
    const int* mask_r1 = mask + (size_t)(b * SQ + r1) * SQ;

    float m0 = -1e30f, m1 = -1e30f, l0 = 0.0f, l1 = 0.0f;
    float oacc[8][4];
#pragma unroll
    for (int nf = 0; nf < 8; ++nf)
#pragma unroll
        for (int r = 0; r < 4; ++r) oacc[nf][r] = 0.0f;

    CP_WAIT0();
    __syncthreads();

    const float* Qs = sm + Q_OFF;
    float* Ps = sm + P_OFF;

    for (int kb = 0; kb < SQ / 64; ++kb) {
        const int s = kb & 1;
        const int k0 = kb * 64;

        // prefetch masked bias (INF sentinel for masked positions)
        float bp[8][4];
#pragma unroll
        for (int nf = 0; nf < 8; ++nf) {
            int kc = k0 + nf * 8 + 2 * t;
            int2 ma = *(const int2*)&mask_r0[kc];
            int2 mb = *(const int2*)&mask_r1[kc];
            bp[nf][0] = ma.x ? FINF : bias_r0[(size_t)kc * NH];
            bp[nf][1] = ma.y ? FINF : bias_r0[(size_t)(kc + 1) * NH];
            bp[nf][2] = mb.x ? FINF : bias_r1[(size_t)kc * NH];
            bp[nf][3] = mb.y ? FINF : bias_r1[(size_t)(kc + 1) * NH];
        }

        // next K/V chunk
        if (kb + 1 < SQ / 64) {
            const int kn = k0 + 64;
#pragma unroll
            for (int it = 0; it < 2; ++it) {
                int idx = tid + it * 512;
                int row = idx >> 4, c4 = idx & 15;
                cpa16(sb + (uint32_t)(K_OFF(s ^ 1) + row * KSTR + c4 * 4) * 4,
                      kg + (size_t)(kn + row) * 64 + c4 * 4);
                int vr = (row & ~7) | slotf(row & 7);
                cpa16(sb + (uint32_t)(V_OFF(s ^ 1) + vr * VSTR + c4 * 4) * 4,
                      vg + (size_t)(kn + row) * 64 + c4 * 4);
            }
            CP_COMMIT();
        }

        // ---- S = Q K^T ----
        const float* Ksf = sm + K_OFF(s);
        float sacc[8][4];
#pragma unroll
        for (int nf = 0; nf < 8; ++nf)
#pragma unroll
            for (int r = 0; r < 4; ++r) sacc[nf][r] = 0.0f;
#pragma unroll
        for (int ks = 0; ks < 8; ++ks) {
            float2 qa = *(const float2*)&Qs[rl * QSTR + ks * 8 + 2 * t];
            float2 qb = *(const float2*)&Qs[(rl + 8) * QSTR + ks * 8 + 2 * t];
#pragma unroll
            for (int nf = 0; nf < 8; ++nf) {
                float2 kp = *(const float2*)&Ksf[(nf * 8 + g) * KSTR + ks * 8 + 2 * t];
                mma8(sacc[nf],
                     __float_as_uint(qa.x), __float_as_uint(qb.x),
                     __float_as_uint(qa.y), __float_as_uint(qb.y),
                     __float_as_uint(kp.x), __float_as_uint(kp.y));
            }
        }

        // ---- fold scale + bias + mask ----
#pragma unroll
        for (int nf = 0; nf < 8; ++nf) {
            sacc[nf][0] = (bp[nf][0] == FINF) ? 1e-14f : fmaf(sacc[nf][0], 0.125f, bp[nf][0]);
            sacc[nf][1] = (bp[nf][1] == FINF) ? 1e-14f : fmaf(sacc[nf][1], 0.125f, bp[nf][1]);
            sacc[nf][2] = (bp[nf][2] == FINF) ? 1e-14f : fmaf(sacc[nf][2], 0.125f, bp[nf][2]);
            sacc[nf][3] = (bp[nf][3] == FINF) ? 1e-14f : fmaf(sacc[nf][3], 0.125f, bp[nf][3]);
        }

        // ---- online softmax ----
        float mx0 = -1e30f, mx1 = -1e30f;
#pragma unroll
        for (int nf = 0; nf < 8; ++nf) {
            mx0 = fmaxf(mx0, fmaxf(sacc[nf][0], sacc[nf][1]));
            mx1 = fmaxf(mx1, fmaxf(sacc[nf][2], sacc[nf][3]));
        }
        mx0 = fmaxf(mx0, __shfl_xor_sync(0xffffffffu, mx0, 1));
        mx0 = fmaxf(mx0, __shfl_xor_sync(0xffffffffu, mx0, 2));
        mx1 = fmaxf(mx1, __shfl_xor_sync(0xffffffffu, mx1, 1));
        mx1 = fmaxf(mx1, __shfl_xor_sync(0xffffffffu, mx1, 2));
        float mn0 = fmaxf(m0, mx0), mn1 = fmaxf(m1, mx1);
        float al0 = __expf(m0 - mn0), al1 = __expf(m1 - mn1);
        m0 = mn0; m1 = mn1;
        float rs0 = 0.0f, rs1 = 0.0f;
#pragma unroll
        for (int nf = 0; nf < 8; ++nf) {
            sacc[nf][0] = __expf(sacc[nf][0] - mn0);
            sacc[nf][1] = __expf(sacc[nf][1] - mn0);
            sacc[nf][2] = __expf(sacc[nf][2] - mn1);
            sacc[nf][3] = __expf(sacc[nf][3] - mn1);
            rs0 += sacc[nf][0] + sacc[nf][1];
            rs1 += sacc[nf][2] + sacc[nf][3];
        }
        rs0 += __shfl_xor_sync(0xffffffffu, rs0, 1);
        rs0 += __shfl_xor_sync(0xffffffffu, rs0, 2);
        rs1 += __shfl_xor_sync(0xffffffffu, rs1, 1);
        rs1 += __shfl_xor_sync(0xffffffffu, rs1, 2);
        l0 = l0 * al0 + rs0;
        l1 = l1 * al1 + rs1;
#pragma unroll
        for (int nf = 0; nf < 8; ++nf) {
            oacc[nf][0] *= al0; oacc[nf][1] *= al0;
            oacc[nf][2] *= al1; oacc[nf][3] *= al1;
        }

        // ---- P (tf32, sigma cols) -> smem ----
        {
            int s0 = slotf(2 * t), s1 = slotf(2 * t + 1);
#pragma unroll
            for (int nf = 0; nf < 8; ++nf) {
                Ps[rl * PSTR + nf * 8 + s0] = f2tff(sacc[nf][0]);
                Ps[rl * PSTR + nf * 8 + s1] = f2tff(sacc[nf][1]);
                Ps[(rl + 8) * PSTR + nf * 8 + s0] = f2tff(sacc[nf][2]);
                Ps[(rl + 8) * PSTR + nf * 8 + s1] = f2tff(sacc[nf][3]);
            }
        }
        __syncwarp();

        // ---- O += P V ----
        const float* Vsf = sm + V_OFF(s);
#pragma unroll
        for (int ks = 0; ks < 8; ++ks) {
            float2 pa = *(const float2*)&Ps[rl * PSTR + ks * 8 + 2 * t];
            float2 pb = *(const float2*)&Ps[(rl + 8) * PSTR + ks * 8 + 2 * t];
#pragma unroll
            for (int nf = 0; nf < 8; ++nf) {
                float vb0 = Vsf[(ks * 8 + 2 * t) * VSTR + nf * 8 + g];
                float vb1 = Vsf[(ks * 8 + 2 * t + 1) * VSTR + nf * 8 + g];
                mma8(oacc[nf],
                     __float_as_uint(pa.x), __float_as_uint(pb.x),
                     __float_as_uint(pa.y), __float_as_uint(pb.y),
                     __float_as_uint(vb0), __float_as_uint(vb1));
            }
        }

        if (kb + 1 < SQ / 64) CP_WAIT0();
        __syncthreads();
    }

    // ---- normalize + write g_ao (kperm'd tf32 for O-projection) ----
    float inv0 = 1.0f / l0, inv1 = 1.0f / l1;
    int s0 = slotf(2 * t), s1 = slotf(2 * t + 1);
#pragma unroll
    for (int nf = 0; nf < 8; ++nf) {
        int colbase = hh * 64 + nf * 8;
        size_t b0 = (size_t)(b * SQ + r0) * HD + colbase;
        size_t b1 = (size_t)(b * SQ + r1) * HD + colbase;
        g_ao[b0 + s0] = f2tff(oacc[nf][0] * inv0);
        g_ao[b0 + s1] = f2tff(oacc[nf][1] * inv0);
        g_ao[b1 + s0] = f2tff(oacc[nf][2] * inv1);
        g_ao[b1 + s1] = f2tff(oacc[nf][3] * inv1);
    }
}

// ---------------------------------------------------------------------------
extern "C" void kernel_launch(void* const* d_in, const int* in_sizes, int n_in,
                              void* d_out, int out_size)
{
    const float* h  = (const float*)d_in[0];
    const float* ab = (const float*)d_in[1];
    const int*   mk = (const int*)d_in[2];
    const float* Wq = (const float*)d_in[3];
    const float* bq = (const float*)d_in[4];
    const float* Wk = (const float*)d_in[5];
    const float* bk = (const float*)d_in[6];
    const float* Wv = (const float*)d_in[7];
    const float* bv = (const float*)d_in[8];
    const float* Wo = (const float*)d_in[9];
    const float* bo = (const float*)d_in[10];
    float* out = (float*)d_out;

    cudaFuncSetAttribute(gemm_tc,
                         cudaFuncAttributeMaxDynamicSharedMemorySize, GEMM_SMEM);
    cudaFuncSetAttribute(attn_kernel,
                         cudaFuncAttributeMaxDynamicSharedMemorySize, ATTN_SMEM);

    prep<<<(MROWS*HD + 255) / 256, 256>>>(h, Wq, Wk, Wv, Wo);
    // fused QKV projection
    gemm_tc<<<dim3(HD / 128, MROWS / 128, 3), 256, GEMM_SMEM>>>(
        bq, bk, bv, nullptr, 1);
    // attention
    attn_kernel<<<dim3(BHCOUNT, SQ / 256), 512, ATTN_SMEM>>>(ab, mk);
    // output projection
    gemm_tc<<<dim3(HD / 128, MROWS / 128, 1), 256, GEMM_SMEM>>>(
        bo, bo, bo, out, 0);
}

// round 6
// speedup vs baseline: 1.0271x; 1.0271x over previous
#include <cuda_runtime.h>
#include <cstdint>

// Problem constants
#define SQ 1024
#define HD 768
#define NH 12
#define DH 64
#define NB 8
#define BHCOUNT (NB*NH)   // 96
#define MROWS (NB*SQ)     // 8192

// Scratch (device globals; tf32 bit patterns stored as float)
__device__ float g_q[BHCOUNT*SQ*DH];    // dperm'd tf32
__device__ float g_k[BHCOUNT*SQ*DH];    // dperm'd tf32
__device__ float g_v[BHCOUNT*SQ*DH];    // natural tf32
__device__ float g_ao[MROWS*HD];        // kperm'd tf32
__device__ float g_ht[MROWS*HD];        // kperm'd tf32 input h
__device__ float g_wt4[4*HD*HD];        // tf32 weights (natural)

// ---------------------------------------------------------------------------
// helpers
// ---------------------------------------------------------------------------
__device__ __forceinline__ uint32_t f2tf(float x) {
    uint32_t r;
    asm("cvt.rna.tf32.f32 %0, %1;" : "=r"(r) : "f"(x));
    return r;
}
__device__ __forceinline__ float f2tff(float x) { return __uint_as_float(f2tf(x)); }
__device__ __forceinline__ int slotf(int c) { return 2*(c&3) + ((c&4)>>2); }

__device__ __forceinline__ void mma8(float* c,
                                     uint32_t a0, uint32_t a1, uint32_t a2, uint32_t a3,
                                     uint32_t b0, uint32_t b1) {
    asm volatile(
        "mma.sync.aligned.m16n8k8.row.col.f32.tf32.tf32.f32 "
        "{%0,%1,%2,%3}, {%4,%5,%6,%7}, {%8,%9}, {%0,%1,%2,%3};"
        : "+f"(c[0]), "+f"(c[1]), "+f"(c[2]), "+f"(c[3])
        : "r"(a0), "r"(a1), "r"(a2), "r"(a3), "r"(b0), "r"(b1));
}

__device__ __forceinline__ uint32_t smem_u32(const void* p) {
    uint32_t a;
    asm("{ .reg .u64 t; cvta.to.shared.u64 t, %1; cvt.u32.u64 %0, t; }"
        : "=r"(a) : "l"(p));
    return a;
}
__device__ __forceinline__ void cpa16(uint32_t dst, const void* src) {
    asm volatile("cp.async.cg.shared.global [%0], [%1], 16;" :: "r"(dst), "l"(src));
}
#define CP_COMMIT() asm volatile("cp.async.commit_group;" ::: "memory")
#define CP_WAIT0()  asm volatile("cp.async.wait_group 0;" ::: "memory")
#define CP_WAIT1()  asm volatile("cp.async.wait_group 1;" ::: "memory")

// ---------------------------------------------------------------------------
// prep: pre-round h (with k-perm) and the 4 weights (natural) to tf32
// ---------------------------------------------------------------------------
__global__ void prep(const float* __restrict__ h,
                     const float* __restrict__ wq, const float* __restrict__ wk,
                     const float* __restrict__ wv, const float* __restrict__ wo)
{
    int i = blockIdx.x * 256 + threadIdx.x;
    if (i < MROWS*HD) {
        int k = i & 7;
        g_ht[i - k + slotf(k)] = f2tff(h[i]);
    }
    if (i < 4*HD*HD) {
        int z = i / (HD*HD), r = i - z*(HD*HD);
        const float* w = (z == 0) ? wq : (z == 1 ? wk : (z == 2 ? wv : wo));
        g_wt4[i] = f2tff(w[r]);
    }
}

// ---------------------------------------------------------------------------
// tf32 GEMM via mma.sync, cp.async double-buffered, 2 CTAs/SM. (unchanged R5)
// ---------------------------------------------------------------------------
#define GA 40
#define GB 132
#define A_ST (128*GA)
#define B_ST (32*GB)
#define STAGE (A_ST + B_ST)
#define NCHUNK (HD/32)
#define GEMM_SMEM (2*STAGE*4)

__global__ __launch_bounds__(256, 2) void gemm_tc(
    const float* __restrict__ bias0, const float* __restrict__ bias1,
    const float* __restrict__ bias2, float* __restrict__ Cout, int mode)
{
    extern __shared__ float sm[];
    const uint32_t sb = smem_u32(sm);
    const int tid = threadIdx.x;
    const int wid = tid >> 5, lane = tid & 31;
    const int wm = wid >> 2, wn = wid & 3;
    const int g = lane >> 2, t = lane & 3;
    const int z = (mode == 1) ? blockIdx.z : 0;

    const float* A = (mode == 0) ? g_ao : g_ht;
    const float* W = g_wt4 + (size_t)((mode == 0) ? 3 : z) * HD * HD;
    const float* bias = (z == 0) ? bias0 : (z == 1 ? bias1 : bias2);
    float* C = (mode == 0) ? Cout : (z == 0 ? g_q : (z == 1 ? g_k : g_v));

    const int m0 = blockIdx.y * 128;
    const int n0 = blockIdx.x * 128;

    float acc[4][4][4];
#pragma unroll
    for (int i = 0; i < 4; ++i)
#pragma unroll
        for (int j = 0; j < 4; ++j)
#pragma unroll
            for (int r = 0; r < 4; ++r) acc[i][j][r] = 0.0f;

#define G_LOAD(cc, st) do { \
    int k0 = (cc) * 32; \
    uint32_t abase = sb + (uint32_t)((st) * STAGE) * 4; \
    uint32_t bbase = abase + A_ST * 4; \
    _Pragma("unroll") \
    for (int it = 0; it < 4; ++it) { \
        int idx = tid + it * 256; \
        int ar = idx >> 3, ac = idx & 7; \
        cpa16(abase + (uint32_t)(ar * GA + ac * 4) * 4, \
              A + (size_t)(m0 + ar) * HD + k0 + ac * 4); \
        int br = idx >> 5, bc = idx & 31; \
        int sr = (br & ~7) | slotf(br & 7); \
        cpa16(bbase + (uint32_t)(sr * GB + bc * 4) * 4, \
              W + (size_t)(k0 + br) * HD + n0 + bc * 4); \
    } \
    CP_COMMIT(); \
} while (0)

    G_LOAD(0, 0);

    for (int c = 0; c < NCHUNK; ++c) {
        const int s = c & 1;
        if (c + 1 < NCHUNK) { G_LOAD(c + 1, s ^ 1); CP_WAIT1(); }
        else CP_WAIT0();
        __syncthreads();

        const float* As = sm + s * STAGE;
        const float* Bs = As + A_ST;
#pragma unroll
        for (int ks = 0; ks < 4; ++ks) {
            float2 ap[4][2];
#pragma unroll
            for (int mf = 0; mf < 4; ++mf) {
                const float* p = As + (wm * 64 + mf * 16 + g) * GA + ks * 8 + 2 * t;
                ap[mf][0] = *(const float2*)p;
                ap[mf][1] = *(const float2*)(p + 8 * GA);
            }
            float bf[4][2];
#pragma unroll
            for (int nf = 0; nf < 4; ++nf) {
                const float* p = Bs + (ks * 8 + 2 * t) * GB + wn * 32 + nf * 8 + g;
                bf[nf][0] = p[0];
                bf[nf][1] = p[GB];
            }
#pragma unroll
            for (int mf = 0; mf < 4; ++mf)
#pragma unroll
                for (int nf = 0; nf < 4; ++nf)
                    mma8(acc[mf][nf],
                         __float_as_uint(ap[mf][0].x), __float_as_uint(ap[mf][1].x),
                         __float_as_uint(ap[mf][0].y), __float_as_uint(ap[mf][1].y),
                         __float_as_uint(bf[nf][0]), __float_as_uint(bf[nf][1]));
        }
        __syncthreads();
    }

    // epilogue
#pragma unroll
    for (int mf = 0; mf < 4; ++mf) {
#pragma unroll
        for (int nf = 0; nf < 4; ++nf) {
            int r0 = m0 + wm * 64 + mf * 16 + g;
            int ncol0 = n0 + wn * 32 + nf * 8 + 2 * t;
            int ncol1 = ncol0 + 1;
            float bb0 = bias[ncol0], bb1 = bias[ncol1];
            float v00 = acc[mf][nf][0] + bb0, v01 = acc[mf][nf][1] + bb1;
            float v10 = acc[mf][nf][2] + bb0, v11 = acc[mf][nf][3] + bb1;
            if (mode == 0) {
                *(float2*)&C[(size_t)r0 * HD + ncol0] = make_float2(v00, v01);
                *(float2*)&C[(size_t)(r0 + 8) * HD + ncol0] = make_float2(v10, v11);
            } else {
                int b = r0 >> 10, sidx = r0 & 1023;
                if (z < 2) {
                    int pc0 = (ncol0 & ~7) | slotf(ncol0 & 7);
                    int pc1 = (ncol1 & ~7) | slotf(ncol1 & 7);
                    int hh = pc0 >> 6;
                    size_t base = ((size_t)(b * NH + hh) * SQ + sidx) * DH;
                    C[base + (pc0 & 63)] = f2tff(v00);
                    C[base + (pc1 & 63)] = f2tff(v01);
                    C[base + 8 * DH + (pc0 & 63)] = f2tff(v10);
                    C[base + 8 * DH + (pc1 & 63)] = f2tff(v11);
                } else {
                    int hh = ncol0 >> 6, dd = ncol0 & 63;
                    size_t base = ((size_t)(b * NH + hh) * SQ + sidx) * DH + dd;
                    *(float2*)&C[base] = make_float2(f2tff(v00), f2tff(v01));
                    *(float2*)&C[base + 8 * DH] = make_float2(f2tff(v10), f2tff(v11));
                }
            }
        }
    }
}

// ---------------------------------------------------------------------------
// Flash attention: 256 threads (8 warps), 128 q-rows/CTA, Q fragments in regs,
// K/V cp.async double-buffered, fixed-max softmax (no rescale, no per-chunk
// reductions), deferred l-reduction.
// smem floats: K[2][64][72] (dperm cols), V[2][64][68] (sigma rows),
//              P[128][72] (sigma cols; also Q staging in prologue).
// ---------------------------------------------------------------------------
#define KSTR 72
#define VSTR 68
#define PSTR 72
#define K_OFF(s) ((s)*64*KSTR)
#define V_OFF(s) (2*64*KSTR + (s)*64*VSTR)
#define P_OFF    (2*64*KSTR + 2*64*VSTR)
#define ATTN_SMEM ((P_OFF + 128*PSTR) * 4)   // 108544 bytes

__global__ __launch_bounds__(256) void attn_kernel(
    const float* __restrict__ bias, const int* __restrict__ mask)
{
    extern __shared__ float sm[];
    const uint32_t sb = smem_u32(sm);
    const float FINF = __int_as_float(0x7f800000);

    const int bh = blockIdx.x;
    const int b = bh / NH, hh = bh - b * NH;
    const int q0 = blockIdx.y * 128;
    const int tid = threadIdx.x;
    const int wid = tid >> 5, lane = tid & 31;
    const int g = lane >> 2, t = lane & 3;
    const int rl = wid * 16 + g;

    const float* qg = g_q + ((size_t)bh * SQ + q0) * DH;
    const float* kg = g_k + (size_t)bh * SQ * DH;
    const float* vg = g_v + (size_t)bh * SQ * DH;

    float* Ps = sm + P_OFF;

    // prologue: stage Q into Ps + chunk0 K/V (one cp.async group)
#pragma unroll
    for (int it = 0; it < 8; ++it) {
        int idx = tid + it * 256;
        int row = idx >> 4, c4 = idx & 15;
        cpa16(sb + (uint32_t)(P_OFF + row * PSTR + c4 * 4) * 4,
              qg + (size_t)row * 64 + c4 * 4);
    }
#pragma unroll
    for (int it = 0; it < 4; ++it) {
        int idx = tid + it * 256;
        int row = idx >> 4, c4 = idx & 15;
        cpa16(sb + (uint32_t)(K_OFF(0) + row * KSTR + c4 * 4) * 4,
              kg + (size_t)row * 64 + c4 * 4);
        int vr = (row & ~7) | slotf(row & 7);
        cpa16(sb + (uint32_t)(V_OFF(0) + vr * VSTR + c4 * 4) * 4,
              vg + (size_t)row * 64 + c4 * 4);
    }
    CP_COMMIT();
    CP_WAIT0();
    __syncthreads();

    // extract Q fragments (dperm'd: float2 at 2t = logical {t, t+4})
    float2 qa[8], qb[8];
#pragma unroll
    for (int ks = 0; ks < 8; ++ks) {
        qa[ks] = *(const float2*)&Ps[rl * PSTR + ks * 8 + 2 * t];
        qb[ks] = *(const float2*)&Ps[(rl + 8) * PSTR + ks * 8 + 2 * t];
    }
    __syncthreads();   // all Q extractions done before Ps reused for P

    const int r0 = q0 + rl, r1 = r0 + 8;
    const float* bias_r0 = bias + ((size_t)(b * SQ + r0) * SQ) * NH + hh;
    const float* bias_r1 = bias + ((size_t)(b * SQ + r1) * SQ) * NH + hh;
    const int* mask_r0 = mask + (size_t)(b * SQ + r0) * SQ;
    const int* mask_r1 = mask + (size_t)(b * SQ + r1) * SQ;

    float l0 = 0.0f, l1 = 0.0f;
    float oacc[8][4];
#pragma unroll
    for (int nf = 0; nf < 8; ++nf)
#pragma unroll
        for (int r = 0; r < 4; ++r) oacc[nf][r] = 0.0f;

    for (int kb = 0; kb < SQ / 64; ++kb) {
        const int s = kb & 1;
        const int k0 = kb * 64;

        // prefetch bias-16 (FINF sentinel for masked)
        float bp[8][4];
#pragma unroll
        for (int nf = 0; nf < 8; ++nf) {
            int kc = k0 + nf * 8 + 2 * t;
            int2 ma = *(const int2*)&mask_r0[kc];
            int2 mb = *(const int2*)&mask_r1[kc];
            bp[nf][0] = ma.x ? FINF : bias_r0[(size_t)kc * NH] - 16.0f;
            bp[nf][1] = ma.y ? FINF : bias_r0[(size_t)(kc + 1) * NH] - 16.0f;
            bp[nf][2] = mb.x ? FINF : bias_r1[(size_t)kc * NH] - 16.0f;
            bp[nf][3] = mb.y ? FINF : bias_r1[(size_t)(kc + 1) * NH] - 16.0f;
        }

        // next K/V chunk
        if (kb + 1 < SQ / 64) {
            const int kn = k0 + 64;
#pragma unroll
            for (int it = 0; it < 4; ++it) {
                int idx = tid + it * 256;
                int row = idx >> 4, c4 = idx & 15;
                cpa16(sb + (uint32_t)(K_OFF(s ^ 1) + row * KSTR + c4 * 4) * 4,
                      kg + (size_t)(kn + row) * 64 + c4 * 4);
                int vr = (row & ~7) | slotf(row & 7);
                cpa16(sb + (uint32_t)(V_OFF(s ^ 1) + vr * VSTR + c4 * 4) * 4,
                      vg + (size_t)(kn + row) * 64 + c4 * 4);
            }
            CP_COMMIT();
        }

        // ---- S = Q K^T ----
        const float* Ksf = sm + K_OFF(s);
        float sacc[8][4];
#pragma unroll
        for (int nf = 0; nf < 8; ++nf)
#pragma unroll
            for (int r = 0; r < 4; ++r) sacc[nf][r] = 0.0f;
#pragma unroll
        for (int ks = 0; ks < 8; ++ks) {
#pragma unroll
            for (int nf = 0; nf < 8; ++nf) {
                float2 kp = *(const float2*)&Ksf[(nf * 8 + g) * KSTR + ks * 8 + 2 * t];
                mma8(sacc[nf],
                     __float_as_uint(qa[ks].x), __float_as_uint(qb[ks].x),
                     __float_as_uint(qa[ks].y), __float_as_uint(qb[ks].y),
                     __float_as_uint(kp.x), __float_as_uint(kp.y));
            }
        }

        // ---- fold scale+bias+mask, exp(s-16), accumulate partial sums ----
        float rs0 = 0.0f, rs1 = 0.0f;
#pragma unroll
        for (int nf = 0; nf < 8; ++nf) {
            float s0 = (bp[nf][0] == FINF) ? -16.0f : fmaf(sacc[nf][0], 0.125f, bp[nf][0]);
            float s1 = (bp[nf][1] == FINF) ? -16.0f : fmaf(sacc[nf][1], 0.125f, bp[nf][1]);
            float s2 = (bp[nf][2] == FINF) ? -16.0f : fmaf(sacc[nf][2], 0.125f, bp[nf][2]);
            float s3 = (bp[nf][3] == FINF) ? -16.0f : fmaf(sacc[nf][3], 0.125f, bp[nf][3]);
            sacc[nf][0] = __expf(s0);
            sacc[nf][1] = __expf(s1);
            sacc[nf][2] = __expf(s2);
            sacc[nf][3] = __expf(s3);
            rs0 += sacc[nf][0] + sacc[nf][1];
            rs1 += sacc[nf][2] + sacc[nf][3];
        }
        l0 += rs0;
        l1 += rs1;

        // ---- P (tf32, sigma cols) -> smem ----
        {
            int s0 = slotf(2 * t), s1 = slotf(2 * t + 1);
#pragma unroll
            for (int nf = 0; nf < 8; ++nf) {
                Ps[rl * PSTR + nf * 8 + s0] = f2tff(sacc[nf][0]);
                Ps[rl * PSTR + nf * 8 + s1] = f2tff(sacc[nf][1]);
                Ps[(rl + 8) * PSTR + nf * 8 + s0] = f2tff(sacc[nf][2]);
                Ps[(rl + 8) * PSTR + nf * 8 + s1] = f2tff(sacc[nf][3]);
            }
        }
        __syncwarp();

        // ---- O += P V ----
        const float* Vsf = sm + V_OFF(s);
#pragma unroll
        for (int ks = 0; ks < 8; ++ks) {
            float2 pa = *(const float2*)&Ps[rl * PSTR + ks * 8 + 2 * t];
            float2 pb = *(const float2*)&Ps[(rl + 8) * PSTR + ks * 8 + 2 * t];
#pragma unroll
            for (int nf = 0; nf < 8; ++nf) {
                float vb0 = Vsf[(ks * 8 + 2 * t) * VSTR + nf * 8 + g];
                float vb1 = Vsf[(ks * 8 + 2 * t + 1) * VSTR + nf * 8 + g];
                mma8(oacc[nf],
                     __float_as_uint(pa.x), __float_as_uint(pb.x),
                     __float_as_uint(pa.y), __float_as_uint(pb.y),
                     __float_as_uint(vb0), __float_as_uint(vb1));
            }
        }

        if (kb + 1 < SQ / 64) CP_WAIT0();
        __syncthreads();
    }

    // ---- final l reduction (quad) + normalize + write g_ao (kperm tf32) ----
    l0 += __shfl_xor_sync(0xffffffffu, l0, 1);
    l0 += __shfl_xor_sync(0xffffffffu, l0, 2);
    l1 += __shfl_xor_sync(0xffffffffu, l1, 1);
    l1 += __shfl_xor_sync(0xffffffffu, l1, 2);
    float inv0 = 1.0f / l0, inv1 = 1.0f / l1;
    int s0 = slotf(2 * t), s1 = slotf(2 * t + 1);
#pragma unroll
    for (int nf = 0; nf < 8; ++nf) {
        int colbase = hh * 64 + nf * 8;
        size_t b0 = (size_t)(b * SQ + r0) * HD + colbase;
        size_t b1 = (size_t)(b * SQ + r1) * HD + colbase;
        g_ao[b0 + s0] = f2tff(oacc[nf][0] * inv0);
        g_ao[b0 + s1] = f2tff(oacc[nf][1] * inv0);
        g_ao[b1 + s0] = f2tff(oacc[nf][2] * inv1);
        g_ao[b1 + s1] = f2tff(oacc[nf][3] * inv1);
    }
}

// ---------------------------------------------------------------------------
extern "C" void kernel_launch(void* const* d_in, const int* in_sizes, int n_in,
                              void* d_out, int out_size)
{
    const float* h  = (const float*)d_in[0];
    const float* ab = (const float*)d_in[1];
    const int*   mk = (const int*)d_in[2];
    const float* Wq = (const float*)d_in[3];
    const float* bq = (const float*)d_in[4];
    const float* Wk = (const float*)d_in[5];
    const float* bk = (const float*)d_in[6];
    const float* Wv = (const float*)d_in[7];
    const float* bv = (const float*)d_in[8];
    const float* Wo = (const float*)d_in[9];
    const float* bo = (const float*)d_in[10];
    float* out = (float*)d_out;

    cudaFuncSetAttribute(gemm_tc,
                         cudaFuncAttributeMaxDynamicSharedMemorySize, GEMM_SMEM);
    cudaFuncSetAttribute(attn_kernel,
                         cudaFuncAttributeMaxDynamicSharedMemorySize, ATTN_SMEM);

    prep<<<(MROWS*HD + 255) / 256, 256>>>(h, Wq, Wk, Wv, Wo);
    gemm_tc<<<dim3(HD / 128, MROWS / 128, 3), 256, GEMM_SMEM>>>(
        bq, bk, bv, nullptr, 1);
    attn_kernel<<<dim3(BHCOUNT, SQ / 128), 256, ATTN_SMEM>>>(ab, mk);
    gemm_tc<<<dim3(HD / 128, MROWS / 128, 1), 256, GEMM_SMEM>>>(
        bo, bo, bo, out, 0);
}

// round 7
// speedup vs baseline: 1.2059x; 1.1741x over previous
#include <cuda_runtime.h>
#include <cstdint>

// Problem constants
#define SQ 1024
#define HD 768
#define NH 12
#define DH 64
#define NB 8
#define BHCOUNT (NB*NH)   // 96
#define MROWS (NB*SQ)     // 8192

// Scratch (device globals; tf32 bit patterns stored as float)
__device__ float g_q[BHCOUNT*SQ*DH];    // natural head-major tf32
__device__ float g_k[BHCOUNT*SQ*DH];    // natural head-major tf32
__device__ float g_v[BHCOUNT*SQ*DH];    // natural head-major tf32
__device__ float g_ao[MROWS*HD];        // kperm'd tf32 (for O-proj A-path)
__device__ float g_ht[MROWS*HD];        // kperm'd tf32 input h
__device__ float g_wt4[4*HD*HD];        // tf32 weights (natural)

// ---------------------------------------------------------------------------
// helpers
// ---------------------------------------------------------------------------
__device__ __forceinline__ uint32_t f2tf(float x) {
    uint32_t r;
    asm("cvt.rna.tf32.f32 %0, %1;" : "=r"(r) : "f"(x));
    return r;
}
__device__ __forceinline__ float f2tff(float x) { return __uint_as_float(f2tf(x)); }
__device__ __forceinline__ int slotf(int c) { return 2*(c&3) + ((c&4)>>2); }

__device__ __forceinline__ void mma8(float* c,
                                     uint32_t a0, uint32_t a1, uint32_t a2, uint32_t a3,
                                     uint32_t b0, uint32_t b1) {
    asm volatile(
        "mma.sync.aligned.m16n8k8.row.col.f32.tf32.tf32.f32 "
        "{%0,%1,%2,%3}, {%4,%5,%6,%7}, {%8,%9}, {%0,%1,%2,%3};"
        : "+f"(c[0]), "+f"(c[1]), "+f"(c[2]), "+f"(c[3])
        : "r"(a0), "r"(a1), "r"(a2), "r"(a3), "r"(b0), "r"(b1));
}

__device__ __forceinline__ uint32_t smem_u32(const void* p) {
    uint32_t a;
    asm("{ .reg .u64 t; cvta.to.shared.u64 t, %1; cvt.u32.u64 %0, t; }"
        : "=r"(a) : "l"(p));
    return a;
}
__device__ __forceinline__ void cpa16(uint32_t dst, const void* src) {
    asm volatile("cp.async.cg.shared.global [%0], [%1], 16;" :: "r"(dst), "l"(src));
}
#define CP_COMMIT() asm volatile("cp.async.commit_group;" ::: "memory")
#define CP_WAIT0()  asm volatile("cp.async.wait_group 0;" ::: "memory")
#define CP_WAIT1()  asm volatile("cp.async.wait_group 1;" ::: "memory")

// ---------------------------------------------------------------------------
// prep: g_ht = kperm'd tf32(h); g_wt4 = tf32(weights), natural
// ---------------------------------------------------------------------------
__global__ void prep(const float* __restrict__ h,
                     const float* __restrict__ wq, const float* __restrict__ wk,
                     const float* __restrict__ wv, const float* __restrict__ wo)
{
    int i = blockIdx.x * 256 + threadIdx.x;
    if (i < MROWS*HD) {
        int k = i & 7;
        g_ht[i - k + slotf(k)] = f2tff(h[i]);
    }
    if (i < 4*HD*HD) {
        int z = i / (HD*HD), r = i - z*(HD*HD);
        const float* w = (z == 0) ? wq : (z == 1 ? wk : (z == 2 ? wv : wo));
        g_wt4[i] = f2tff(w[r]);
    }
}

// ---------------------------------------------------------------------------
// tf32 GEMM: cp.async double-buffered, 2 CTAs/SM (measured R5/R6 winner).
// mode 1 (QKV, z=blockIdx.z): out = natural head-major tf32 (g_q/g_k/g_v).
// mode 0 (O-proj): A = g_ao (kperm tf32), out = Cout fp32 row-major.
// ---------------------------------------------------------------------------
#define GA 40
#define GB 132
#define A_ST (128*GA)
#define B_ST (32*GB)
#define STAGE (A_ST + B_ST)
#define NCHUNK (HD/32)
#define GEMM_SMEM (2*STAGE*4)

__global__ __launch_bounds__(256, 2) void gemm_tc(
    const float* __restrict__ bias0, const float* __restrict__ bias1,
    const float* __restrict__ bias2, float* __restrict__ Cout, int mode)
{
    extern __shared__ float sm[];
    const uint32_t sb = smem_u32(sm);
    const int tid = threadIdx.x;
    const int wid = tid >> 5, lane = tid & 31;
    const int wm = wid >> 2, wn = wid & 3;
    const int g = lane >> 2, t = lane & 3;
    const int z = (mode == 1) ? blockIdx.z : 0;

    const float* A = (mode == 0) ? g_ao : g_ht;
    const float* W = g_wt4 + (size_t)((mode == 0) ? 3 : z) * HD * HD;
    const float* bias = (z == 0) ? bias0 : (z == 1 ? bias1 : bias2);
    float* C = (mode == 0) ? Cout : (z == 0 ? g_q : (z == 1 ? g_k : g_v));

    const int m0 = blockIdx.y * 128;
    const int n0 = blockIdx.x * 128;

    float acc[4][4][4];
#pragma unroll
    for (int i = 0; i < 4; ++i)
#pragma unroll
        for (int j = 0; j < 4; ++j)
#pragma unroll
            for (int r = 0; r < 4; ++r) acc[i][j][r] = 0.0f;

#define G_LOAD(cc, st) do { \
    int k0 = (cc) * 32; \
    uint32_t abase = sb + (uint32_t)((st) * STAGE) * 4; \
    uint32_t bbase = abase + A_ST * 4; \
    _Pragma("unroll") \
    for (int it = 0; it < 4; ++it) { \
        int idx = tid + it * 256; \
        int ar = idx >> 3, ac = idx & 7; \
        cpa16(abase + (uint32_t)(ar * GA + ac * 4) * 4, \
              A + (size_t)(m0 + ar) * HD + k0 + ac * 4); \
        int br = idx >> 5, bc = idx & 31; \
        int sr = (br & ~7) | slotf(br & 7); \
        cpa16(bbase + (uint32_t)(sr * GB + bc * 4) * 4, \
              W + (size_t)(k0 + br) * HD + n0 + bc * 4); \
    } \
    CP_COMMIT(); \
} while (0)

    G_LOAD(0, 0);

    for (int c = 0; c < NCHUNK; ++c) {
        const int s = c & 1;
        if (c + 1 < NCHUNK) { G_LOAD(c + 1, s ^ 1); CP_WAIT1(); }
        else CP_WAIT0();
        __syncthreads();

        const float* As = sm + s * STAGE;
        const float* Bs = As + A_ST;
#pragma unroll
        for (int ks = 0; ks < 4; ++ks) {
            float2 ap[4][2];
#pragma unroll
            for (int mf = 0; mf < 4; ++mf) {
                const float* p = As + (wm * 64 + mf * 16 + g) * GA + ks * 8 + 2 * t;
                ap[mf][0] = *(const float2*)p;
                ap[mf][1] = *(const float2*)(p + 8 * GA);
            }
            float bf[4][2];
#pragma unroll
            for (int nf = 0; nf < 4; ++nf) {
                const float* p = Bs + (ks * 8 + 2 * t) * GB + wn * 32 + nf * 8 + g;
                bf[nf][0] = p[0];
                bf[nf][1] = p[GB];
            }
#pragma unroll
            for (int mf = 0; mf < 4; ++mf)
#pragma unroll
                for (int nf = 0; nf < 4; ++nf)
                    mma8(acc[mf][nf],
                         __float_as_uint(ap[mf][0].x), __float_as_uint(ap[mf][1].x),
                         __float_as_uint(ap[mf][0].y), __float_as_uint(ap[mf][1].y),
                         __float_as_uint(bf[nf][0]), __float_as_uint(bf[nf][1]));
        }
        __syncthreads();
    }

    // epilogue
#pragma unroll
    for (int mf = 0; mf < 4; ++mf) {
#pragma unroll
        for (int nf = 0; nf < 4; ++nf) {
            int r0 = m0 + wm * 64 + mf * 16 + g;
            int ncol0 = n0 + wn * 32 + nf * 8 + 2 * t;
            float bb0 = bias[ncol0], bb1 = bias[ncol0 + 1];
            float v00 = acc[mf][nf][0] + bb0, v01 = acc[mf][nf][1] + bb1;
            float v10 = acc[mf][nf][2] + bb0, v11 = acc[mf][nf][3] + bb1;
            if (mode == 0) {
                *(float2*)&C[(size_t)r0 * HD + ncol0] = make_float2(v00, v01);
                *(float2*)&C[(size_t)(r0 + 8) * HD + ncol0] = make_float2(v10, v11);
            } else {
                // natural head-major tf32 (R4 attention's expected layout)
                int b = r0 >> 10, sidx = r0 & 1023;
                int hh = ncol0 >> 6, dd = ncol0 & 63;
                size_t base = ((size_t)(b * NH + hh) * SQ + sidx) * DH + dd;
                *(float2*)&C[base] = make_float2(f2tff(v00), f2tff(v01));
                *(float2*)&C[base + 8 * DH] = make_float2(f2tff(v10), f2tff(v11));
            }
        }
    }
}

// ---------------------------------------------------------------------------
// Flash attention — R4 structure verbatim (256 thr, natural layouts, scalar
// fragment feeds) + fixed-max softmax (bias-16, no rescale, deferred l).
// smem floats: K[2][64][68], V[2][64][72], Ps[128][68] (Q staging + P).
// ---------------------------------------------------------------------------
#define KSTR 68
#define VSTR 72
#define K_OFF(s)  ((s)*64*KSTR)
#define V_OFF(s)  (2*64*KSTR + (s)*64*VSTR)
#define P_OFF     (2*64*KSTR + 2*64*VSTR)
#define ATTN_FLOATS (P_OFF + 128*KSTR)
#define ATTN_SMEM (ATTN_FLOATS*4)   // 106496 bytes

__global__ __launch_bounds__(256) void attn_kernel(
    const float* __restrict__ bias, const int* __restrict__ mask)
{
    extern __shared__ float sm[];
    const uint32_t sb = smem_u32(sm);
    float* Ps = sm + P_OFF;

    const int bh = blockIdx.x;
    const int b = bh / NH, hh = bh - b * NH;
    const int q0 = blockIdx.y * 128;
    const int tid = threadIdx.x;
    const int wid = tid >> 5, lane = tid & 31;
    const int g = lane >> 2, t = lane & 3;
    const int rl = wid * 16 + g;

    const float* qg = g_q + ((size_t)bh * SQ + q0) * DH;
    const float* kg = g_k + (size_t)bh * SQ * DH;
    const float* vg = g_v + (size_t)bh * SQ * DH;

    // issue chunk-0 K/V cp.async first (overlaps Q staging)
#pragma unroll
    for (int it = 0; it < 4; ++it) {
        int idx = tid + it * 256;
        int row = idx >> 4, c4 = idx & 15;
        cpa16(sb + (uint32_t)(K_OFF(0) + row * KSTR + c4 * 4) * 4,
              kg + (size_t)row * 64 + c4 * 4);
        cpa16(sb + (uint32_t)(V_OFF(0) + row * VSTR + c4 * 4) * 4,
              vg + (size_t)row * 64 + c4 * 4);
    }
    CP_COMMIT();

    // stage Q tile (128x64) into Ps, then extract fragments to registers
#pragma unroll
    for (int it = 0; it < 8; ++it) {
        int idx = tid + it * 256;
        int row = idx >> 4, c4 = idx & 15;
        *(float4*)&Ps[row * KSTR + c4 * 4] = *(const float4*)&qg[(size_t)row * 64 + c4 * 4];
    }
    __syncthreads();
    uint32_t qf[8][4];
#pragma unroll
    for (int ks = 0; ks < 8; ++ks) {
        qf[ks][0] = __float_as_uint(Ps[rl * KSTR + ks * 8 + t]);
        qf[ks][1] = __float_as_uint(Ps[(rl + 8) * KSTR + ks * 8 + t]);
        qf[ks][2] = __float_as_uint(Ps[rl * KSTR + ks * 8 + t + 4]);
        qf[ks][3] = __float_as_uint(Ps[(rl + 8) * KSTR + ks * 8 + t + 4]);
    }
    CP_WAIT0();
    __syncthreads();

    const int r0 = q0 + rl;
    const int r1 = r0 + 8;
    const float* bias_r0 = bias + ((size_t)(b * SQ + r0) * SQ) * NH + hh;
    const float* bias_r1 = bias + ((size_t)(b * SQ + r1) * SQ) * NH + hh;
    const int* mask_r0 = mask + (size_t)(b * SQ + r0) * SQ;
    const int* mask_r1 = mask + (size_t)(b * SQ + r1) * SQ;

    float l0 = 0.0f, l1 = 0.0f;
    float oacc[8][4];
#pragma unroll
    for (int nf = 0; nf < 8; ++nf)
#pragma unroll
        for (int r = 0; r < 4; ++r) oacc[nf][r] = 0.0f;

    for (int kb = 0; kb < SQ / 64; ++kb) {
        const int s = kb & 1;
        const int k0 = kb * 64;

        // ---- prefetch (bias - 16) + mask ----
        float bp[8][4];
        int mp[8][4];
#pragma unroll
        for (int nf = 0; nf < 8; ++nf) {
            int kc = k0 + nf * 8 + 2 * t;
            int2 ma = *(const int2*)&mask_r0[kc];
            int2 mb = *(const int2*)&mask_r1[kc];
            mp[nf][0] = ma.x; mp[nf][1] = ma.y; mp[nf][2] = mb.x; mp[nf][3] = mb.y;
            bp[nf][0] = bias_r0[(size_t)kc * NH] - 16.0f;
            bp[nf][1] = bias_r0[(size_t)(kc + 1) * NH] - 16.0f;
            bp[nf][2] = bias_r1[(size_t)kc * NH] - 16.0f;
            bp[nf][3] = bias_r1[(size_t)(kc + 1) * NH] - 16.0f;
        }

        // ---- cp.async next K/V chunk ----
        if (kb + 1 < SQ / 64) {
            const int kn = k0 + 64;
#pragma unroll
            for (int it = 0; it < 4; ++it) {
                int idx = tid + it * 256;
                int row = idx >> 4, c4 = idx & 15;
                cpa16(sb + (uint32_t)(K_OFF(s ^ 1) + row * KSTR + c4 * 4) * 4,
                      kg + (size_t)(kn + row) * 64 + c4 * 4);
                cpa16(sb + (uint32_t)(V_OFF(s ^ 1) + row * VSTR + c4 * 4) * 4,
                      vg + (size_t)(kn + row) * 64 + c4 * 4);
            }
            CP_COMMIT();
        }

        // ---- S = Q K^T ----
        const float* Ksf = sm + K_OFF(s);
        float sacc[8][4];
#pragma unroll
        for (int nf = 0; nf < 8; ++nf)
#pragma unroll
            for (int r = 0; r < 4; ++r) sacc[nf][r] = 0.0f;
#pragma unroll
        for (int ks = 0; ks < 8; ++ks) {
#pragma unroll
            for (int nf = 0; nf < 8; ++nf) {
                const float* kp = Ksf + (nf * 8 + g) * KSTR + ks * 8 + t;
                mma8(sacc[nf], qf[ks][0], qf[ks][1], qf[ks][2], qf[ks][3],
                     __float_as_uint(kp[0]), __float_as_uint(kp[4]));
            }
        }

        // ---- fold scale+bias+mask, exp(s-16), accumulate partial sums ----
        float rs0 = 0.0f, rs1 = 0.0f;
#pragma unroll
        for (int nf = 0; nf < 8; ++nf) {
            float s0 = mp[nf][0] ? -16.0f : fmaf(sacc[nf][0], 0.125f, bp[nf][0]);
            float s1 = mp[nf][1] ? -16.0f : fmaf(sacc[nf][1], 0.125f, bp[nf][1]);
            float s2 = mp[nf][2] ? -16.0f : fmaf(sacc[nf][2], 0.125f, bp[nf][2]);
            float s3 = mp[nf][3] ? -16.0f : fmaf(sacc[nf][3], 0.125f, bp[nf][3]);
            sacc[nf][0] = __expf(s0);
            sacc[nf][1] = __expf(s1);
            sacc[nf][2] = __expf(s2);
            sacc[nf][3] = __expf(s3);
            rs0 += sacc[nf][0] + sacc[nf][1];
            rs1 += sacc[nf][2] + sacc[nf][3];
        }
        l0 += rs0;
        l1 += rs1;

        // ---- P (tf32 bits) -> smem, warp-local rows ----
#pragma unroll
        for (int nf = 0; nf < 8; ++nf) {
            int kc = nf * 8 + 2 * t;
            *(float2*)&Ps[rl * KSTR + kc] =
                make_float2(f2tff(sacc[nf][0]), f2tff(sacc[nf][1]));
            *(float2*)&Ps[(rl + 8) * KSTR + kc] =
                make_float2(f2tff(sacc[nf][2]), f2tff(sacc[nf][3]));
        }
        __syncwarp();

        // ---- O += P V ----
        const float* Vsf = sm + V_OFF(s);
#pragma unroll
        for (int ks = 0; ks < 8; ++ks) {
            const float* pp = Ps + rl * KSTR + ks * 8 + t;
            uint32_t a0 = __float_as_uint(pp[0]);
            uint32_t a1 = __float_as_uint(pp[8 * KSTR]);
            uint32_t a2 = __float_as_uint(pp[4]);
            uint32_t a3 = __float_as_uint(pp[8 * KSTR + 4]);
#pragma unroll
            for (int nf = 0; nf < 8; ++nf) {
                const float* vp = Vsf + (ks * 8 + t) * VSTR + nf * 8 + g;
                mma8(oacc[nf], a0, a1, a2, a3,
                     __float_as_uint(vp[0]), __float_as_uint(vp[4 * VSTR]));
            }
        }

        if (kb + 1 < SQ / 64) CP_WAIT0();
        __syncthreads();
    }

    // ---- final l reduction (quad) + normalize + write g_ao (kperm tf32) ----
    l0 += __shfl_xor_sync(0xffffffffu, l0, 1);
    l0 += __shfl_xor_sync(0xffffffffu, l0, 2);
    l1 += __shfl_xor_sync(0xffffffffu, l1, 1);
    l1 += __shfl_xor_sync(0xffffffffu, l1, 2);
    float inv0 = 1.0f / l0, inv1 = 1.0f / l1;
    int s0 = slotf(2 * t), s1 = slotf(2 * t + 1);
#pragma unroll
    for (int nf = 0; nf < 8; ++nf) {
        int colbase = hh * 64 + nf * 8;
        size_t b0 = (size_t)(b * SQ + r0) * HD + colbase;
        size_t b1 = (size_t)(b * SQ + r1) * HD + colbase;
        g_ao[b0 + s0] = f2tff(oacc[nf][0] * inv0);
        g_ao[b0 + s1] = f2tff(oacc[nf][1] * inv0);
        g_ao[b1 + s0] = f2tff(oacc[nf][2] * inv1);
        g_ao[b1 + s1] = f2tff(oacc[nf][3] * inv1);
    }
}

// ---------------------------------------------------------------------------
extern "C" void kernel_launch(void* const* d_in, const int* in_sizes, int n_in,
                              void* d_out, int out_size)
{
    const float* h  = (const float*)d_in[0];
    const float* ab = (const float*)d_in[1];
    const int*   mk = (const int*)d_in[2];
    const float* Wq = (const float*)d_in[3];
    const float* bq = (const float*)d_in[4];
    const float* Wk = (const float*)d_in[5];
    const float* bk = (const float*)d_in[6];
    const float* Wv = (const float*)d_in[7];
    const float* bv = (const float*)d_in[8];
    const float* Wo = (const float*)d_in[9];
    const float* bo = (const float*)d_in[10];
    float* out = (float*)d_out;

    cudaFuncSetAttribute(gemm_tc,
                         cudaFuncAttributeMaxDynamicSharedMemorySize, GEMM_SMEM);
    cudaFuncSetAttribute(attn_kernel,
                         cudaFuncAttributeMaxDynamicSharedMemorySize, ATTN_SMEM);

    prep<<<(MROWS*HD + 255) / 256, 256>>>(h, Wq, Wk, Wv, Wo);
    gemm_tc<<<dim3(HD / 128, MROWS / 128, 3), 256, GEMM_SMEM>>>(
        bq, bk, bv, nullptr, 1);
    attn_kernel<<<dim3(BHCOUNT, SQ / 128), 256, ATTN_SMEM>>>(ab, mk);
    gemm_tc<<<dim3(HD / 128, MROWS / 128, 1), 256, GEMM_SMEM>>>(
        bo, bo, bo, out, 0);
}

// round 8
// speedup vs baseline: 1.3509x; 1.1202x over previous
#include <cuda_runtime.h>
#include <cstdint>

// Problem constants
#define SQ 1024
#define HD 768
#define NH 12
#define DH 64
#define NB 8
#define BHCOUNT (NB*NH)   // 96
#define MROWS (NB*SQ)     // 8192

// Scratch (device globals; tf32 bit patterns stored as float)
__device__ float g_q[BHCOUNT*SQ*DH];    // natural head-major tf32
__device__ float g_k[BHCOUNT*SQ*DH];    // natural head-major tf32
__device__ float g_v[BHCOUNT*SQ*DH];    // natural head-major tf32
__device__ float g_ao[MROWS*HD];        // kperm'd tf32 (for O-proj A-path)
__device__ float g_ht[MROWS*HD];        // kperm'd tf32 input h
__device__ float g_wt4[4*HD*HD];        // tf32 weights (natural)
__device__ float g_bm[(size_t)BHCOUNT*SQ*SQ];  // bias-16 (FINF if masked), [b][h][q][k]

// ---------------------------------------------------------------------------
// helpers
// ---------------------------------------------------------------------------
__device__ __forceinline__ uint32_t f2tf(float x) {
    uint32_t r;
    asm("cvt.rna.tf32.f32 %0, %1;" : "=r"(r) : "f"(x));
    return r;
}
__device__ __forceinline__ float f2tff(float x) { return __uint_as_float(f2tf(x)); }
__device__ __forceinline__ int slotf(int c) { return 2*(c&3) + ((c&4)>>2); }

__device__ __forceinline__ void mma8(float* c,
                                     uint32_t a0, uint32_t a1, uint32_t a2, uint32_t a3,
                                     uint32_t b0, uint32_t b1) {
    asm volatile(
        "mma.sync.aligned.m16n8k8.row.col.f32.tf32.tf32.f32 "
        "{%0,%1,%2,%3}, {%4,%5,%6,%7}, {%8,%9}, {%0,%1,%2,%3};"
        : "+f"(c[0]), "+f"(c[1]), "+f"(c[2]), "+f"(c[3])
        : "r"(a0), "r"(a1), "r"(a2), "r"(a3), "r"(b0), "r"(b1));
}

__device__ __forceinline__ uint32_t smem_u32(const void* p) {
    uint32_t a;
    asm("{ .reg .u64 t; cvta.to.shared.u64 t, %1; cvt.u32.u64 %0, t; }"
        : "=r"(a) : "l"(p));
    return a;
}
__device__ __forceinline__ void cpa16(uint32_t dst, const void* src) {
    asm volatile("cp.async.cg.shared.global [%0], [%1], 16;" :: "r"(dst), "l"(src));
}
#define CP_COMMIT() asm volatile("cp.async.commit_group;" ::: "memory")
#define CP_WAIT0()  asm volatile("cp.async.wait_group 0;" ::: "memory")
#define CP_WAIT1()  asm volatile("cp.async.wait_group 1;" ::: "memory")

// ---------------------------------------------------------------------------
// prep: g_ht = kperm'd tf32(h); g_wt4 = tf32(weights), natural
// ---------------------------------------------------------------------------
__global__ void prep(const float* __restrict__ h,
                     const float* __restrict__ wq, const float* __restrict__ wk,
                     const float* __restrict__ wv, const float* __restrict__ wo)
{
    int i = blockIdx.x * 256 + threadIdx.x;
    if (i < MROWS*HD) {
        int k = i & 7;
        g_ht[i - k + slotf(k)] = f2tff(h[i]);
    }
    if (i < 4*HD*HD) {
        int z = i / (HD*HD), r = i - z*(HD*HD);
        const float* w = (z == 0) ? wq : (z == 1 ? wk : (z == 2 ? wv : wo));
        g_wt4[i] = f2tff(w[r]);
    }
}

// ---------------------------------------------------------------------------
// repack: g_bm[(b*NH+h)][q][k] = mask ? +INF : bias[b][q][k][h] - 16
// block per (q, b): coalesced read of the [k][h] row, smem transpose,
// coalesced per-head writes.
// ---------------------------------------------------------------------------
__global__ __launch_bounds__(256) void repack(
    const float* __restrict__ bias, const int* __restrict__ mask)
{
    __shared__ float sbias[SQ*NH];   // 48 KB
    __shared__ int   smask[SQ];      // 4 KB
    const int q = blockIdx.x, b = blockIdx.y;
    const int tid = threadIdx.x;
    const float FINF = __int_as_float(0x7f800000);

    const float* bsrc = bias + ((size_t)(b * SQ + q) * SQ) * NH;
#pragma unroll
    for (int it = 0; it < 12; ++it) {
        int i4 = (tid + it * 256) * 4;
        *(float4*)&sbias[i4] = *(const float4*)&bsrc[i4];
    }
    {
        const int* msrc = mask + (size_t)(b * SQ + q) * SQ;
        int i4 = tid * 4;
        *(int4*)&smask[i4] = *(const int4*)&msrc[i4];
    }
    __syncthreads();

#pragma unroll
    for (int h = 0; h < NH; ++h) {
        float* dst = g_bm + (((size_t)(b * NH + h) * SQ + q) * SQ);
        int k4 = tid * 4;
        float4 o;
        o.x = smask[k4 + 0] ? FINF : sbias[(k4 + 0) * NH + h] - 16.0f;
        o.y = smask[k4 + 1] ? FINF : sbias[(k4 + 1) * NH + h] - 16.0f;
        o.z = smask[k4 + 2] ? FINF : sbias[(k4 + 2) * NH + h] - 16.0f;
        o.w = smask[k4 + 3] ? FINF : sbias[(k4 + 3) * NH + h] - 16.0f;
        *(float4*)&dst[k4] = o;
    }
}

// ---------------------------------------------------------------------------
// tf32 GEMM: cp.async 3-stage pipeline, 1 sync/chunk, 2 CTAs/SM.
// mode 1 (QKV, z=blockIdx.z): out = natural head-major tf32 (g_q/g_k/g_v).
// mode 0 (O-proj): A = g_ao (kperm tf32), out = Cout fp32 row-major.
// ---------------------------------------------------------------------------
#define GA 40
#define GB 132
#define A_ST (128*GA)
#define B_ST (32*GB)
#define STAGE (A_ST + B_ST)
#define NCHUNK (HD/32)
#define NSTAGE 3
#define GEMM_SMEM (NSTAGE*STAGE*4)   // 112128 bytes

__global__ __launch_bounds__(256, 2) void gemm_tc(
    const float* __restrict__ bias0, const float* __restrict__ bias1,
    const float* __restrict__ bias2, float* __restrict__ Cout, int mode)
{
    extern __shared__ float sm[];
    const uint32_t sb = smem_u32(sm);
    const int tid = threadIdx.x;
    const int wid = tid >> 5, lane = tid & 31;
    const int wm = wid >> 2, wn = wid & 3;
    const int g = lane >> 2, t = lane & 3;
    const int z = (mode == 1) ? blockIdx.z : 0;

    const float* A = (mode == 0) ? g_ao : g_ht;
    const float* W = g_wt4 + (size_t)((mode == 0) ? 3 : z) * HD * HD;
    const float* bias = (z == 0) ? bias0 : (z == 1 ? bias1 : bias2);
    float* C = (mode == 0) ? Cout : (z == 0 ? g_q : (z == 1 ? g_k : g_v));

    const int m0 = blockIdx.y * 128;
    const int n0 = blockIdx.x * 128;

    float acc[4][4][4];
#pragma unroll
    for (int i = 0; i < 4; ++i)
#pragma unroll
        for (int j = 0; j < 4; ++j)
#pragma unroll
            for (int r = 0; r < 4; ++r) acc[i][j][r] = 0.0f;

#define G_LOAD(cc, st) do { \
    int k0 = (cc) * 32; \
    uint32_t abase = sb + (uint32_t)((st) * STAGE) * 4; \
    uint32_t bbase = abase + A_ST * 4; \
    _Pragma("unroll") \
    for (int it = 0; it < 4; ++it) { \
        int idx = tid + it * 256; \
        int ar = idx >> 3, ac = idx & 7; \
        cpa16(abase + (uint32_t)(ar * GA + ac * 4) * 4, \
              A + (size_t)(m0 + ar) * HD + k0 + ac * 4); \
        int br = idx >> 5, bc = idx & 31; \
        int sr = (br & ~7) | slotf(br & 7); \
        cpa16(bbase + (uint32_t)(sr * GB + bc * 4) * 4, \
              W + (size_t)(k0 + br) * HD + n0 + bc * 4); \
    } \
    CP_COMMIT(); \
} while (0)

    G_LOAD(0, 0);
    G_LOAD(1, 1);

    int st = 0;
    for (int c = 0; c < NCHUNK; ++c) {
        CP_WAIT1();          // stage c's group complete (<=1 pending)
        __syncthreads();     // all threads done reading the stage we reuse
        if (c + 2 < NCHUNK) {
            int st2 = st + 2; if (st2 >= NSTAGE) st2 -= NSTAGE;
            G_LOAD(c + 2, st2);
        }

        const float* As = sm + st * STAGE;
        const float* Bs = As + A_ST;
#pragma unroll
        for (int ks = 0; ks < 4; ++ks) {
            float2 ap[4][2];
#pragma unroll
            for (int mf = 0; mf < 4; ++mf) {
                const float* p = As + (wm * 64 + mf * 16 + g) * GA + ks * 8 + 2 * t;
                ap[mf][0] = *(const float2*)p;
                ap[mf][1] = *(const float2*)(p + 8 * GA);
            }
            float bf[4][2];
#pragma unroll
            for (int nf = 0; nf < 4; ++nf) {
                const float* p = Bs + (ks * 8 + 2 * t) * GB + wn * 32 + nf * 8 + g;
                bf[nf][0] = p[0];
                bf[nf][1] = p[GB];
            }
#pragma unroll
            for (int mf = 0; mf < 4; ++mf)
#pragma unroll
                for (int nf = 0; nf < 4; ++nf)
                    mma8(acc[mf][nf],
                         __float_as_uint(ap[mf][0].x), __float_as_uint(ap[mf][1].x),
                         __float_as_uint(ap[mf][0].y), __float_as_uint(ap[mf][1].y),
                         __float_as_uint(bf[nf][0]), __float_as_uint(bf[nf][1]));
        }
        if (++st >= NSTAGE) st = 0;
    }

    // epilogue
#pragma unroll
    for (int mf = 0; mf < 4; ++mf) {
#pragma unroll
        for (int nf = 0; nf < 4; ++nf) {
            int r0 = m0 + wm * 64 + mf * 16 + g;
            int ncol0 = n0 + wn * 32 + nf * 8 + 2 * t;
            float bb0 = bias[ncol0], bb1 = bias[ncol0 + 1];
            float v00 = acc[mf][nf][0] + bb0, v01 = acc[mf][nf][1] + bb1;
            float v10 = acc[mf][nf][2] + bb0, v11 = acc[mf][nf][3] + bb1;
            if (mode == 0) {
                *(float2*)&C[(size_t)r0 * HD + ncol0] = make_float2(v00, v01);
                *(float2*)&C[(size_t)(r0 + 8) * HD + ncol0] = make_float2(v10, v11);
            } else {
                int b = r0 >> 10, sidx = r0 & 1023;
                int hh = ncol0 >> 6, dd = ncol0 & 63;
                size_t base = ((size_t)(b * NH + hh) * SQ + sidx) * DH + dd;
                *(float2*)&C[base] = make_float2(f2tff(v00), f2tff(v01));
                *(float2*)&C[base + 8 * DH] = make_float2(f2tff(v10), f2tff(v11));
            }
        }
    }
}

// ---------------------------------------------------------------------------
// Flash attention — R7 structure + coalesced g_bm loads (mask pre-folded).
// smem floats: K[2][64][68], V[2][64][72], Ps[128][68] (Q staging + P).
// ---------------------------------------------------------------------------
#define KSTR 68
#define VSTR 72
#define K_OFF(s)  ((s)*64*KSTR)
#define V_OFF(s)  (2*64*KSTR + (s)*64*VSTR)
#define P_OFF     (2*64*KSTR + 2*64*VSTR)
#define ATTN_FLOATS (P_OFF + 128*KSTR)
#define ATTN_SMEM (ATTN_FLOATS*4)   // 106496 bytes

__global__ __launch_bounds__(256) void attn_kernel()
{
    extern __shared__ float sm[];
    const uint32_t sb = smem_u32(sm);
    const float FINF = __int_as_float(0x7f800000);
    float* Ps = sm + P_OFF;

    const int bh = blockIdx.x;
    const int b = bh / NH, hh = bh - b * NH;
    const int q0 = blockIdx.y * 128;
    const int tid = threadIdx.x;
    const int wid = tid >> 5, lane = tid & 31;
    const int g = lane >> 2, t = lane & 3;
    const int rl = wid * 16 + g;

    const float* qg = g_q + ((size_t)bh * SQ + q0) * DH;
    const float* kg = g_k + (size_t)bh * SQ * DH;
    const float* vg = g_v + (size_t)bh * SQ * DH;

    // issue chunk-0 K/V cp.async first (overlaps Q staging)
#pragma unroll
    for (int it = 0; it < 4; ++it) {
        int idx = tid + it * 256;
        int row = idx >> 4, c4 = idx & 15;
        cpa16(sb + (uint32_t)(K_OFF(0) + row * KSTR + c4 * 4) * 4,
              kg + (size_t)row * 64 + c4 * 4);
        cpa16(sb + (uint32_t)(V_OFF(0) + row * VSTR + c4 * 4) * 4,
              vg + (size_t)row * 64 + c4 * 4);
    }
    CP_COMMIT();

    // stage Q tile (128x64) into Ps, then extract fragments to registers
#pragma unroll
    for (int it = 0; it < 8; ++it) {
        int idx = tid + it * 256;
        int row = idx >> 4, c4 = idx & 15;
        *(float4*)&Ps[row * KSTR + c4 * 4] = *(const float4*)&qg[(size_t)row * 64 + c4 * 4];
    }
    __syncthreads();
    uint32_t qf[8][4];
#pragma unroll
    for (int ks = 0; ks < 8; ++ks) {
        qf[ks][0] = __float_as_uint(Ps[rl * KSTR + ks * 8 + t]);
        qf[ks][1] = __float_as_uint(Ps[(rl + 8) * KSTR + ks * 8 + t]);
        qf[ks][2] = __float_as_uint(Ps[rl * KSTR + ks * 8 + t + 4]);
        qf[ks][3] = __float_as_uint(Ps[(rl + 8) * KSTR + ks * 8 + t + 4]);
    }
    CP_WAIT0();
    __syncthreads();

    const int r0 = q0 + rl;
    const int r1 = r0 + 8;
    const float* bm_r0 = g_bm + ((size_t)bh * SQ + r0) * SQ;
    const float* bm_r1 = g_bm + ((size_t)bh * SQ + r1) * SQ;

    float l0 = 0.0f, l1 = 0.0f;
    float oacc[8][4];
#pragma unroll
    for (int nf = 0; nf < 8; ++nf)
#pragma unroll
        for (int r = 0; r < 4; ++r) oacc[nf][r] = 0.0f;

    for (int kb = 0; kb < SQ / 64; ++kb) {
        const int s = kb & 1;
        const int k0 = kb * 64;

        // ---- prefetch bm (bias-16, FINF = masked), coalesced float2 ----
        float bp[8][4];
#pragma unroll
        for (int nf = 0; nf < 8; ++nf) {
            int kc = k0 + nf * 8 + 2 * t;
            float2 u = *(const float2*)&bm_r0[kc];
            float2 v = *(const float2*)&bm_r1[kc];
            bp[nf][0] = u.x; bp[nf][1] = u.y; bp[nf][2] = v.x; bp[nf][3] = v.y;
        }

        // ---- cp.async next K/V chunk ----
        if (kb + 1 < SQ / 64) {
            const int kn = k0 + 64;
#pragma unroll
            for (int it = 0; it < 4; ++it) {
                int idx = tid + it * 256;
                int row = idx >> 4, c4 = idx & 15;
                cpa16(sb + (uint32_t)(K_OFF(s ^ 1) + row * KSTR + c4 * 4) * 4,
                      kg + (size_t)(kn + row) * 64 + c4 * 4);
                cpa16(sb + (uint32_t)(V_OFF(s ^ 1) + row * VSTR + c4 * 4) * 4,
                      vg + (size_t)(kn + row) * 64 + c4 * 4);
            }
            CP_COMMIT();
        }

        // ---- S = Q K^T ----
        const float* Ksf = sm + K_OFF(s);
        float sacc[8][4];
#pragma unroll
        for (int nf = 0; nf < 8; ++nf)
#pragma unroll
            for (int r = 0; r < 4; ++r) sacc[nf][r] = 0.0f;
#pragma unroll
        for (int ks = 0; ks < 8; ++ks) {
#pragma unroll
            for (int nf = 0; nf < 8; ++nf) {
                const float* kp = Ksf + (nf * 8 + g) * KSTR + ks * 8 + t;
                mma8(sacc[nf], qf[ks][0], qf[ks][1], qf[ks][2], qf[ks][3],
                     __float_as_uint(kp[0]), __float_as_uint(kp[4]));
            }
        }

        // ---- fold scale+bias (masked -> -16), exp, partial sums ----
        float rs0 = 0.0f, rs1 = 0.0f;
#pragma unroll
        for (int nf = 0; nf < 8; ++nf) {
            float s0 = (bp[nf][0] == FINF) ? -16.0f : fmaf(sacc[nf][0], 0.125f, bp[nf][0]);
            float s1 = (bp[nf][1] == FINF) ? -16.0f : fmaf(sacc[nf][1], 0.125f, bp[nf][1]);
            float s2 = (bp[nf][2] == FINF) ? -16.0f : fmaf(sacc[nf][2], 0.125f, bp[nf][2]);
            float s3 = (bp[nf][3] == FINF) ? -16.0f : fmaf(sacc[nf][3], 0.125f, bp[nf][3]);
            sacc[nf][0] = __expf(s0);
            sacc[nf][1] = __expf(s1);
            sacc[nf][2] = __expf(s2);
            sacc[nf][3] = __expf(s3);
            rs0 += sacc[nf][0] + sacc[nf][1];
            rs1 += sacc[nf][2] + sacc[nf][3];
        }
        l0 += rs0;
        l1 += rs1;

        // ---- P (tf32 bits) -> smem, warp-local rows ----
#pragma unroll
        for (int nf = 0; nf < 8; ++nf) {
            int kc = nf * 8 + 2 * t;
            *(float2*)&Ps[rl * KSTR + kc] =
                make_float2(f2tff(sacc[nf][0]), f2tff(sacc[nf][1]));
            *(float2*)&Ps[(rl + 8) * KSTR + kc] =
                make_float2(f2tff(sacc[nf][2]), f2tff(sacc[nf][3]));
        }
        __syncwarp();

        // ---- O += P V ----
        const float* Vsf = sm + V_OFF(s);
#pragma unroll
        for (int ks = 0; ks < 8; ++ks) {
            const float* pp = Ps + rl * KSTR + ks * 8 + t;
            uint32_t a0 = __float_as_uint(pp[0]);
            uint32_t a1 = __float_as_uint(pp[8 * KSTR]);
            uint32_t a2 = __float_as_uint(pp[4]);
            uint32_t a3 = __float_as_uint(pp[8 * KSTR + 4]);
#pragma unroll
            for (int nf = 0; nf < 8; ++nf) {
                const float* vp = Vsf + (ks * 8 + t) * VSTR + nf * 8 + g;
                mma8(oacc[nf], a0, a1, a2, a3,
                     __float_as_uint(vp[0]), __float_as_uint(vp[4 * VSTR]));
            }
        }

        if (kb + 1 < SQ / 64) CP_WAIT0();
        __syncthreads();
    }

    // ---- final l reduction (quad) + normalize + write g_ao (kperm tf32) ----
    l0 += __shfl_xor_sync(0xffffffffu, l0, 1);
    l0 += __shfl_xor_sync(0xffffffffu, l0, 2);
    l1 += __shfl_xor_sync(0xffffffffu, l1, 1);
    l1 += __shfl_xor_sync(0xffffffffu, l1, 2);
    float inv0 = 1.0f / l0, inv1 = 1.0f / l1;
    int s0 = slotf(2 * t), s1 = slotf(2 * t + 1);
#pragma unroll
    for (int nf = 0; nf < 8; ++nf) {
        int colbase = hh * 64 + nf * 8;
        size_t b0 = (size_t)(b * SQ + r0) * HD + colbase;
        size_t b1 = (size_t)(b * SQ + r1) * HD + colbase;
        g_ao[b0 + s0] = f2tff(oacc[nf][0] * inv0);
        g_ao[b0 + s1] = f2tff(oacc[nf][1] * inv0);
        g_ao[b1 + s0] = f2tff(oacc[nf][2] * inv1);
        g_ao[b1 + s1] = f2tff(oacc[nf][3] * inv1);
    }
}

// ---------------------------------------------------------------------------
extern "C" void kernel_launch(void* const* d_in, const int* in_sizes, int n_in,
                              void* d_out, int out_size)
{
    const float* h  = (const float*)d_in[0];
    const float* ab = (const float*)d_in[1];
    const int*   mk = (const int*)d_in[2];
    const float* Wq = (const float*)d_in[3];
    const float* bq = (const float*)d_in[4];
    const float* Wk = (const float*)d_in[5];
    const float* bk = (const float*)d_in[6];
    const float* Wv = (const float*)d_in[7];
    const float* bv = (const float*)d_in[8];
    const float* Wo = (const float*)d_in[9];
    const float* bo = (const float*)d_in[10];
    float* out = (float*)d_out;

    cudaFuncSetAttribute(gemm_tc,
                         cudaFuncAttributeMaxDynamicSharedMemorySize, GEMM_SMEM);
    cudaFuncSetAttribute(attn_kernel,
                         cudaFuncAttributeMaxDynamicSharedMemorySize, ATTN_SMEM);

    prep<<<(MROWS*HD + 255) / 256, 256>>>(h, Wq, Wk, Wv, Wo);
    repack<<<dim3(SQ, NB), 256>>>(ab, mk);
    gemm_tc<<<dim3(HD / 128, MROWS / 128, 3), 256, GEMM_SMEM>>>(
        bq, bk, bv, nullptr, 1);
    attn_kernel<<<dim3(BHCOUNT, SQ / 128), 256, ATTN_SMEM>>>();
    gemm_tc<<<dim3(HD / 128, MROWS / 128, 1), 256, GEMM_SMEM>>>(
        bo, bo, bo, out, 0);
}

// round 9
// speedup vs baseline: 1.4360x; 1.0630x over previous
#include <cuda_runtime.h>
#include <cstdint>

// Problem constants
#define SQ 1024
#define HD 768
#define NH 12
#define DH 64
#define NB 8
#define BHCOUNT (NB*NH)   // 96
#define MROWS (NB*SQ)     // 8192

// Scratch (device globals; tf32 bit patterns stored as float)
__device__ float g_q[BHCOUNT*SQ*DH];    // natural head-major tf32
__device__ float g_k[BHCOUNT*SQ*DH];    // natural head-major tf32
__device__ float g_v[BHCOUNT*SQ*DH];    // natural head-major tf32
__device__ float g_ao[MROWS*HD];        // kperm'd tf32 (for O-proj A-path)
__device__ float g_ht[MROWS*HD];        // kperm'd tf32 input h
__device__ float g_wt4[4*HD*HD];        // tf32 weights (natural)
__device__ float g_bm[(size_t)BHCOUNT*SQ*SQ];  // bias-16 (FINF if masked), [b][h][q][k]

// ---------------------------------------------------------------------------
// helpers
// ---------------------------------------------------------------------------
__device__ __forceinline__ uint32_t f2tf(float x) {
    uint32_t r;
    asm("cvt.rna.tf32.f32 %0, %1;" : "=r"(r) : "f"(x));
    return r;
}
__device__ __forceinline__ float f2tff(float x) { return __uint_as_float(f2tf(x)); }
__device__ __forceinline__ int slotf(int c) { return 2*(c&3) + ((c&4)>>2); }

__device__ __forceinline__ void mma8(float* c,
                                     uint32_t a0, uint32_t a1, uint32_t a2, uint32_t a3,
                                     uint32_t b0, uint32_t b1) {
    asm volatile(
        "mma.sync.aligned.m16n8k8.row.col.f32.tf32.tf32.f32 "
        "{%0,%1,%2,%3}, {%4,%5,%6,%7}, {%8,%9}, {%0,%1,%2,%3};"
        : "+f"(c[0]), "+f"(c[1]), "+f"(c[2]), "+f"(c[3])
        : "r"(a0), "r"(a1), "r"(a2), "r"(a3), "r"(b0), "r"(b1));
}

__device__ __forceinline__ uint32_t smem_u32(const void* p) {
    uint32_t a;
    asm("{ .reg .u64 t; cvta.to.shared.u64 t, %1; cvt.u32.u64 %0, t; }"
        : "=r"(a) : "l"(p));
    return a;
}
__device__ __forceinline__ void cpa16(uint32_t dst, const void* src) {
    asm volatile("cp.async.cg.shared.global [%0], [%1], 16;" :: "r"(dst), "l"(src));
}
#define CP_COMMIT() asm volatile("cp.async.commit_group;" ::: "memory")
#define CP_WAIT0()  asm volatile("cp.async.wait_group 0;" ::: "memory")
#define CP_WAIT1()  asm volatile("cp.async.wait_group 1;" ::: "memory")

// ---------------------------------------------------------------------------
// prep: g_ht = kperm'd tf32(h); g_wt4 = tf32(weights), natural
// ---------------------------------------------------------------------------
__global__ void prep(const float* __restrict__ h,
                     const float* __restrict__ wq, const float* __restrict__ wk,
                     const float* __restrict__ wv, const float* __restrict__ wo)
{
    int i = blockIdx.x * 256 + threadIdx.x;
    if (i < MROWS*HD) {
        int k = i & 7;
        g_ht[i - k + slotf(k)] = f2tff(h[i]);
    }
    if (i < 4*HD*HD) {
        int z = i / (HD*HD), r = i - z*(HD*HD);
        const float* w = (z == 0) ? wq : (z == 1 ? wk : (z == 2 ? wv : wo));
        g_wt4[i] = f2tff(w[r]);
    }
}

// ---------------------------------------------------------------------------
// repack: g_bm[(b*NH+h)][q][k] = mask ? +INF : bias[b][q][k][h] - 16
// ---------------------------------------------------------------------------
__global__ __launch_bounds__(256) void repack(
    const float* __restrict__ bias, const int* __restrict__ mask)
{
    __shared__ float sbias[SQ*NH];   // 48 KB
    __shared__ int   smask[SQ];      // 4 KB
    const int q = blockIdx.x, b = blockIdx.y;
    const int tid = threadIdx.x;
    const float FINF = __int_as_float(0x7f800000);

    const float* bsrc = bias + ((size_t)(b * SQ + q) * SQ) * NH;
#pragma unroll
    for (int it = 0; it < 12; ++it) {
        int i4 = (tid + it * 256) * 4;
        *(float4*)&sbias[i4] = *(const float4*)&bsrc[i4];
    }
    {
        const int* msrc = mask + (size_t)(b * SQ + q) * SQ;
        int i4 = tid * 4;
        *(int4*)&smask[i4] = *(const int4*)&msrc[i4];
    }
    __syncthreads();

#pragma unroll
    for (int h = 0; h < NH; ++h) {
        float* dst = g_bm + (((size_t)(b * NH + h) * SQ + q) * SQ);
        int k4 = tid * 4;
        float4 o;
        o.x = smask[k4 + 0] ? FINF : sbias[(k4 + 0) * NH + h] - 16.0f;
        o.y = smask[k4 + 1] ? FINF : sbias[(k4 + 1) * NH + h] - 16.0f;
        o.z = smask[k4 + 2] ? FINF : sbias[(k4 + 2) * NH + h] - 16.0f;
        o.w = smask[k4 + 3] ? FINF : sbias[(k4 + 3) * NH + h] - 16.0f;
        *(float4*)&dst[k4] = o;
    }
}

// ---------------------------------------------------------------------------
// tf32 GEMM: cp.async 3-stage pipeline, 1 sync/chunk, 2 CTAs/SM. (R8)
// ---------------------------------------------------------------------------
#define GA 40
#define GB 132
#define A_ST (128*GA)
#define B_ST (32*GB)
#define STAGE (A_ST + B_ST)
#define NCHUNK (HD/32)
#define NSTAGE 3
#define GEMM_SMEM (NSTAGE*STAGE*4)   // 112128 bytes

__global__ __launch_bounds__(256, 2) void gemm_tc(
    const float* __restrict__ bias0, const float* __restrict__ bias1,
    const float* __restrict__ bias2, float* __restrict__ Cout, int mode)
{
    extern __shared__ float sm[];
    const uint32_t sb = smem_u32(sm);
    const int tid = threadIdx.x;
    const int wid = tid >> 5, lane = tid & 31;
    const int wm = wid >> 2, wn = wid & 3;
    const int g = lane >> 2, t = lane & 3;
    const int z = (mode == 1) ? blockIdx.z : 0;

    const float* A = (mode == 0) ? g_ao : g_ht;
    const float* W = g_wt4 + (size_t)((mode == 0) ? 3 : z) * HD * HD;
    const float* bias = (z == 0) ? bias0 : (z == 1 ? bias1 : bias2);
    float* C = (mode == 0) ? Cout : (z == 0 ? g_q : (z == 1 ? g_k : g_v));

    const int m0 = blockIdx.y * 128;
    const int n0 = blockIdx.x * 128;

    float acc[4][4][4];
#pragma unroll
    for (int i = 0; i < 4; ++i)
#pragma unroll
        for (int j = 0; j < 4; ++j)
#pragma unroll
            for (int r = 0; r < 4; ++r) acc[i][j][r] = 0.0f;

#define G_LOAD(cc, st) do { \
    int k0 = (cc) * 32; \
    uint32_t abase = sb + (uint32_t)((st) * STAGE) * 4; \
    uint32_t bbase = abase + A_ST * 4; \
    _Pragma("unroll") \
    for (int it = 0; it < 4; ++it) { \
        int idx = tid + it * 256; \
        int ar = idx >> 3, ac = idx & 7; \
        cpa16(abase + (uint32_t)(ar * GA + ac * 4) * 4, \
              A + (size_t)(m0 + ar) * HD + k0 + ac * 4); \
        int br = idx >> 5, bc = idx & 31; \
        int sr = (br & ~7) | slotf(br & 7); \
        cpa16(bbase + (uint32_t)(sr * GB + bc * 4) * 4, \
              W + (size_t)(k0 + br) * HD + n0 + bc * 4); \
    } \
    CP_COMMIT(); \
} while (0)

    G_LOAD(0, 0);
    G_LOAD(1, 1);

    int st = 0;
    for (int c = 0; c < NCHUNK; ++c) {
        CP_WAIT1();
        __syncthreads();
        if (c + 2 < NCHUNK) {
            int st2 = st + 2; if (st2 >= NSTAGE) st2 -= NSTAGE;
            G_LOAD(c + 2, st2);
        }

        const float* As = sm + st * STAGE;
        const float* Bs = As + A_ST;
#pragma unroll
        for (int ks = 0; ks < 4; ++ks) {
            float2 ap[4][2];
#pragma unroll
            for (int mf = 0; mf < 4; ++mf) {
                const float* p = As + (wm * 64 + mf * 16 + g) * GA + ks * 8 + 2 * t;
                ap[mf][0] = *(const float2*)p;
                ap[mf][1] = *(const float2*)(p + 8 * GA);
            }
            float bf[4][2];
#pragma unroll
            for (int nf = 0; nf < 4; ++nf) {
                const float* p = Bs + (ks * 8 + 2 * t) * GB + wn * 32 + nf * 8 + g;
                bf[nf][0] = p[0];
                bf[nf][1] = p[GB];
            }
#pragma unroll
            for (int mf = 0; mf < 4; ++mf)
#pragma unroll
                for (int nf = 0; nf < 4; ++nf)
                    mma8(acc[mf][nf],
                         __float_as_uint(ap[mf][0].x), __float_as_uint(ap[mf][1].x),
                         __float_as_uint(ap[mf][0].y), __float_as_uint(ap[mf][1].y),
                         __float_as_uint(bf[nf][0]), __float_as_uint(bf[nf][1]));
        }
        if (++st >= NSTAGE) st = 0;
    }

    // epilogue
#pragma unroll
    for (int mf = 0; mf < 4; ++mf) {
#pragma unroll
        for (int nf = 0; nf < 4; ++nf) {
            int r0 = m0 + wm * 64 + mf * 16 + g;
            int ncol0 = n0 + wn * 32 + nf * 8 + 2 * t;
            float bb0 = bias[ncol0], bb1 = bias[ncol0 + 1];
            float v00 = acc[mf][nf][0] + bb0, v01 = acc[mf][nf][1] + bb1;
            float v10 = acc[mf][nf][2] + bb0, v11 = acc[mf][nf][3] + bb1;
            if (mode == 0) {
                *(float2*)&C[(size_t)r0 * HD + ncol0] = make_float2(v00, v01);
                *(float2*)&C[(size_t)(r0 + 8) * HD + ncol0] = make_float2(v10, v11);
            } else {
                int b = r0 >> 10, sidx = r0 & 1023;
                int hh = ncol0 >> 6, dd = ncol0 & 63;
                size_t base = ((size_t)(b * NH + hh) * SQ + sidx) * DH + dd;
                *(float2*)&C[base] = make_float2(f2tff(v00), f2tff(v01));
                *(float2*)&C[base + 8 * DH] = make_float2(f2tff(v10), f2tff(v11));
            }
        }
    }
}

// ---------------------------------------------------------------------------
// Flash attention — R8 structure; bm loaded at fold time (no prefetch array)
// to fit 128 regs -> 2 CTAs/SM.
// smem floats: K[2][64][68], V[2][64][72], Ps[128][68] (Q staging + P).
// ---------------------------------------------------------------------------
#define KSTR 68
#define VSTR 72
#define K_OFF(s)  ((s)*64*KSTR)
#define V_OFF(s)  (2*64*KSTR + (s)*64*VSTR)
#define P_OFF     (2*64*KSTR + 2*64*VSTR)
#define ATTN_FLOATS (P_OFF + 128*KSTR)
#define ATTN_SMEM (ATTN_FLOATS*4)   // 106496 bytes

__global__ __launch_bounds__(256, 2) void attn_kernel()
{
    extern __shared__ float sm[];
    const uint32_t sb = smem_u32(sm);
    const float FINF = __int_as_float(0x7f800000);
    float* Ps = sm + P_OFF;

    const int bh = blockIdx.x;
    const int b = bh / NH, hh = bh - b * NH;
    const int q0 = blockIdx.y * 128;
    const int tid = threadIdx.x;
    const int wid = tid >> 5, lane = tid & 31;
    const int g = lane >> 2, t = lane & 3;
    const int rl = wid * 16 + g;

    const float* qg = g_q + ((size_t)bh * SQ + q0) * DH;
    const float* kg = g_k + (size_t)bh * SQ * DH;
    const float* vg = g_v + (size_t)bh * SQ * DH;

    // issue chunk-0 K/V cp.async first (overlaps Q staging)
#pragma unroll
    for (int it = 0; it < 4; ++it) {
        int idx = tid + it * 256;
        int row = idx >> 4, c4 = idx & 15;
        cpa16(sb + (uint32_t)(K_OFF(0) + row * KSTR + c4 * 4) * 4,
              kg + (size_t)row * 64 + c4 * 4);
        cpa16(sb + (uint32_t)(V_OFF(0) + row * VSTR + c4 * 4) * 4,
              vg + (size_t)row * 64 + c4 * 4);
    }
    CP_COMMIT();

    // stage Q tile (128x64) into Ps, then extract fragments to registers
#pragma unroll
    for (int it = 0; it < 8; ++it) {
        int idx = tid + it * 256;
        int row = idx >> 4, c4 = idx & 15;
        *(float4*)&Ps[row * KSTR + c4 * 4] = *(const float4*)&qg[(size_t)row * 64 + c4 * 4];
    }
    __syncthreads();
    uint32_t qf[8][4];
#pragma unroll
    for (int ks = 0; ks < 8; ++ks) {
        qf[ks][0] = __float_as_uint(Ps[rl * KSTR + ks * 8 + t]);
        qf[ks][1] = __float_as_uint(Ps[(rl + 8) * KSTR + ks * 8 + t]);
        qf[ks][2] = __float_as_uint(Ps[rl * KSTR + ks * 8 + t + 4]);
        qf[ks][3] = __float_as_uint(Ps[(rl + 8) * KSTR + ks * 8 + t + 4]);
    }
    CP_WAIT0();
    __syncthreads();

    const int r0 = q0 + rl;
    const int r1 = r0 + 8;
    const float* bm_r0 = g_bm + ((size_t)bh * SQ + r0) * SQ;
    const float* bm_r1 = g_bm + ((size_t)bh * SQ + r1) * SQ;

    float l0 = 0.0f, l1 = 0.0f;
    float oacc[8][4];
#pragma unroll
    for (int nf = 0; nf < 8; ++nf)
#pragma unroll
        for (int r = 0; r < 4; ++r) oacc[nf][r] = 0.0f;

    for (int kb = 0; kb < SQ / 64; ++kb) {
        const int s = kb & 1;
        const int k0 = kb * 64;

        // ---- cp.async next K/V chunk ----
        if (kb + 1 < SQ / 64) {
            const int kn = k0 + 64;
#pragma unroll
            for (int it = 0; it < 4; ++it) {
                int idx = tid + it * 256;
                int row = idx >> 4, c4 = idx & 15;
                cpa16(sb + (uint32_t)(K_OFF(s ^ 1) + row * KSTR + c4 * 4) * 4,
                      kg + (size_t)(kn + row) * 64 + c4 * 4);
                cpa16(sb + (uint32_t)(V_OFF(s ^ 1) + row * VSTR + c4 * 4) * 4,
                      vg + (size_t)(kn + row) * 64 + c4 * 4);
            }
            CP_COMMIT();
        }

        // ---- S = Q K^T ----
        const float* Ksf = sm + K_OFF(s);
        float sacc[8][4];
#pragma unroll
        for (int nf = 0; nf < 8; ++nf)
#pragma unroll
            for (int r = 0; r < 4; ++r) sacc[nf][r] = 0.0f;
#pragma unroll
        for (int ks = 0; ks < 8; ++ks) {
#pragma unroll
            for (int nf = 0; nf < 8; ++nf) {
                const float* kp = Ksf + (nf * 8 + g) * KSTR + ks * 8 + t;
                mma8(sacc[nf], qf[ks][0], qf[ks][1], qf[ks][2], qf[ks][3],
                     __float_as_uint(kp[0]), __float_as_uint(kp[4]));
            }
        }

        // ---- load bm, fold scale+bias (masked -> -16), exp, partial sums ----
        float rs0 = 0.0f, rs1 = 0.0f;
#pragma unroll
        for (int nf = 0; nf < 8; ++nf) {
            int kc = k0 + nf * 8 + 2 * t;
            float2 u = *(const float2*)&bm_r0[kc];
            float2 v = *(const float2*)&bm_r1[kc];
            float s0 = (u.x == FINF) ? -16.0f : fmaf(sacc[nf][0], 0.125f, u.x);
            float s1 = (u.y == FINF) ? -16.0f : fmaf(sacc[nf][1], 0.125f, u.y);
            float s2 = (v.x == FINF) ? -16.0f : fmaf(sacc[nf][2], 0.125f, v.x);
            float s3 = (v.y == FINF) ? -16.0f : fmaf(sacc[nf][3], 0.125f, v.y);
            sacc[nf][0] = __expf(s0);
            sacc[nf][1] = __expf(s1);
            sacc[nf][2] = __expf(s2);
            sacc[nf][3] = __expf(s3);
            rs0 += sacc[nf][0] + sacc[nf][1];
            rs1 += sacc[nf][2] + sacc[nf][3];
        }
        l0 += rs0;
        l1 += rs1;

        // ---- P (tf32 bits) -> smem, warp-local rows ----
#pragma unroll
        for (int nf = 0; nf < 8; ++nf) {
            int kc = nf * 8 + 2 * t;
            *(float2*)&Ps[rl * KSTR + kc] =
                make_float2(f2tff(sacc[nf][0]), f2tff(sacc[nf][1]));
            *(float2*)&Ps[(rl + 8) * KSTR + kc] =
                make_float2(f2tff(sacc[nf][2]), f2tff(sacc[nf][3]));
        }
        __syncwarp();

        // ---- O += P V ----
        const float* Vsf = sm + V_OFF(s);
#pragma unroll
        for (int ks = 0; ks < 8; ++ks) {
            const float* pp = Ps + rl * KSTR + ks * 8 + t;
            uint32_t a0 = __float_as_uint(pp[0]);
            uint32_t a1 = __float_as_uint(pp[8 * KSTR]);
            uint32_t a2 = __float_as_uint(pp[4]);
            uint32_t a3 = __float_as_uint(pp[8 * KSTR + 4]);
#pragma unroll
            for (int nf = 0; nf < 8; ++nf) {
                const float* vp = Vsf + (ks * 8 + t) * VSTR + nf * 8 + g;
                mma8(oacc[nf], a0, a1, a2, a3,
                     __float_as_uint(vp[0]), __float_as_uint(vp[4 * VSTR]));
            }
        }

        if (kb + 1 < SQ / 64) CP_WAIT0();
        __syncthreads();
    }

    // ---- final l reduction (quad) + normalize + write g_ao (kperm tf32) ----
    l0 += __shfl_xor_sync(0xffffffffu, l0, 1);
    l0 += __shfl_xor_sync(0xffffffffu, l0, 2);
    l1 += __shfl_xor_sync(0xffffffffu, l1, 1);
    l1 += __shfl_xor_sync(0xffffffffu, l1, 2);
    float inv0 = 1.0f / l0, inv1 = 1.0f / l1;
    int s0 = slotf(2 * t), s1 = slotf(2 * t + 1);
#pragma unroll
    for (int nf = 0; nf < 8; ++nf) {
        int colbase = hh * 64 + nf * 8;
        size_t b0 = (size_t)(b * SQ + r0) * HD + colbase;
        size_t b1 = (size_t)(b * SQ + r1) * HD + colbase;
        g_ao[b0 + s0] = f2tff(oacc[nf][0] * inv0);
        g_ao[b0 + s1] = f2tff(oacc[nf][1] * inv0);
        g_ao[b1 + s0] = f2tff(oacc[nf][2] * inv1);
        g_ao[b1 + s1] = f2tff(oacc[nf][3] * inv1);
    }
}

// ---------------------------------------------------------------------------
extern "C" void kernel_launch(void* const* d_in, const int* in_sizes, int n_in,
                              void* d_out, int out_size)
{
    const float* h  = (const float*)d_in[0];
    const float* ab = (const float*)d_in[1];
    const int*   mk = (const int*)d_in[2];
    const float* Wq = (const float*)d_in[3];
    const float* bq = (const float*)d_in[4];
    const float* Wk = (const float*)d_in[5];
    const float* bk = (const float*)d_in[6];
    const float* Wv = (const float*)d_in[7];
    const float* bv = (const float*)d_in[8];
    const float* Wo = (const float*)d_in[9];
    const float* bo = (const float*)d_in[10];
    float* out = (float*)d_out;

    cudaFuncSetAttribute(gemm_tc,
                         cudaFuncAttributeMaxDynamicSharedMemorySize, GEMM_SMEM);
    cudaFuncSetAttribute(attn_kernel,
                         cudaFuncAttributeMaxDynamicSharedMemorySize, ATTN_SMEM);

    prep<<<(MROWS*HD + 255) / 256, 256>>>(h, Wq, Wk, Wv, Wo);
    repack<<<dim3(SQ, NB), 256>>>(ab, mk);
    gemm_tc<<<dim3(HD / 128, MROWS / 128, 3), 256, GEMM_SMEM>>>(
        bq, bk, bv, nullptr, 1);
    attn_kernel<<<dim3(BHCOUNT, SQ / 128), 256, ATTN_SMEM>>>();
    gemm_tc<<<dim3(HD / 128, MROWS / 128, 1), 256, GEMM_SMEM>>>(
        bo, bo, bo, out, 0);
}

// round 10
// speedup vs baseline: 1.5242x; 1.0614x over previous
#include <cuda_runtime.h>
#include <cstdint>

// Problem constants
#define SQ 1024
#define HD 768
#define NH 12
#define DH 64
#define NB 8
#define BHCOUNT (NB*NH)   // 96
#define MROWS (NB*SQ)     // 8192

// Scratch (device globals; tf32 bit patterns stored as float)
__device__ float g_q[BHCOUNT*SQ*DH];    // natural head-major tf32, pre-scaled by 0.125
__device__ float g_k[BHCOUNT*SQ*DH];    // natural head-major tf32
__device__ float g_v[BHCOUNT*SQ*DH];    // natural head-major tf32
__device__ float g_ao[MROWS*HD];        // kperm'd tf32 (for O-proj A-path)
__device__ float g_ht[MROWS*HD];        // kperm'd tf32 input h
__device__ float g_wt4[4*HD*HD];        // tf32 weights (natural)
__device__ float g_bm[(size_t)BHCOUNT*SQ*SQ];  // (bias-16)*log2e, FINF if masked; col-permuted

#define LOG2E 1.4426950408889634f
#define MASKED_ARG (-23.08312065422341f)   // (1e-14 - 16) * log2e

// ---------------------------------------------------------------------------
// helpers
// ---------------------------------------------------------------------------
__device__ __forceinline__ uint32_t f2tf(float x) {
    uint32_t r;
    asm("cvt.rna.tf32.f32 %0, %1;" : "=r"(r) : "f"(x));
    return r;
}
__device__ __forceinline__ float f2tff(float x) { return __uint_as_float(f2tf(x)); }
__device__ __forceinline__ float ex2f(float x) {
    float r;
    asm("ex2.approx.ftz.f32 %0, %1;" : "=f"(r) : "f"(x));
    return r;
}
__device__ __forceinline__ int slotf(int c) { return 2*(c&3) + ((c&4)>>2); }

__device__ __forceinline__ void mma8(float* c,
                                     uint32_t a0, uint32_t a1, uint32_t a2, uint32_t a3,
                                     uint32_t b0, uint32_t b1) {
    asm volatile(
        "mma.sync.aligned.m16n8k8.row.col.f32.tf32.tf32.f32 "
        "{%0,%1,%2,%3}, {%4,%5,%6,%7}, {%8,%9}, {%0,%1,%2,%3};"
        : "+f"(c[0]), "+f"(c[1]), "+f"(c[2]), "+f"(c[3])
        : "r"(a0), "r"(a1), "r"(a2), "r"(a3), "r"(b0), "r"(b1));
}

__device__ __forceinline__ uint32_t smem_u32(const void* p) {
    uint32_t a;
    asm("{ .reg .u64 t; cvta.to.shared.u64 t, %1; cvt.u32.u64 %0, t; }"
        : "=r"(a) : "l"(p));
    return a;
}
__device__ __forceinline__ void cpa16(uint32_t dst, const void* src) {
    asm volatile("cp.async.cg.shared.global [%0], [%1], 16;" :: "r"(dst), "l"(src));
}
#define CP_COMMIT() asm volatile("cp.async.commit_group;" ::: "memory")
#define CP_WAIT0()  asm volatile("cp.async.wait_group 0;" ::: "memory")
#define CP_WAIT1()  asm volatile("cp.async.wait_group 1;" ::: "memory")

// ---------------------------------------------------------------------------
// prep: g_ht = kperm'd tf32(h); g_wt4 = tf32(weights), natural
// ---------------------------------------------------------------------------
__global__ void prep(const float* __restrict__ h,
                     const float* __restrict__ wq, const float* __restrict__ wk,
                     const float* __restrict__ wv, const float* __restrict__ wo)
{
    int i = blockIdx.x * 256 + threadIdx.x;
    if (i < MROWS*HD) {
        int k = i & 7;
        g_ht[i - k + slotf(k)] = f2tff(h[i]);
    }
    if (i < 4*HD*HD) {
        int z = i / (HD*HD), r = i - z*(HD*HD);
        const float* w = (z == 0) ? wq : (z == 1 ? wk : (z == 2 ? wv : wo));
        g_wt4[i] = f2tff(w[r]);
    }
}

// ---------------------------------------------------------------------------
// repack: g_bm[(b*NH+h)][q][perm(k)] = mask ? +INF : (bias[b][q][k][h]-16)*log2e
// perm within each 64-col chunk: pos = t*16 + nf*2 + j  <->  col = nf*8 + 2t + j
// ---------------------------------------------------------------------------
__global__ __launch_bounds__(256) void repack(
    const float* __restrict__ bias, const int* __restrict__ mask)
{
    __shared__ float sbias[SQ*NH];   // 48 KB
    __shared__ int   smask[SQ];      // 4 KB
    const int q = blockIdx.x, b = blockIdx.y;
    const int tid = threadIdx.x;
    const float FINF = __int_as_float(0x7f800000);

    const float* bsrc = bias + ((size_t)(b * SQ + q) * SQ) * NH;
#pragma unroll
    for (int it = 0; it < 12; ++it) {
        int i4 = (tid + it * 256) * 4;
        *(float4*)&sbias[i4] = *(const float4*)&bsrc[i4];
    }
    {
        const int* msrc = mask + (size_t)(b * SQ + q) * SQ;
        int i4 = tid * 4;
        *(int4*)&smask[i4] = *(const int4*)&msrc[i4];
    }
    __syncthreads();

#pragma unroll
    for (int h = 0; h < NH; ++h) {
        float* dst = g_bm + (((size_t)(b * NH + h) * SQ + q) * SQ);
        int p0 = tid * 4;
        float o[4];
#pragma unroll
        for (int e = 0; e < 4; ++e) {
            int p = p0 + e;
            int w = p & 63, t = w >> 4, idx = w & 15;
            int k = (p & ~63) + (idx >> 1) * 8 + 2 * t + (idx & 1);
            o[e] = smask[k] ? FINF : (sbias[k * NH + h] - 16.0f) * LOG2E;
        }
        *(float4*)&dst[p0] = make_float4(o[0], o[1], o[2], o[3]);
    }
}

// ---------------------------------------------------------------------------
// tf32 GEMM: cp.async 3-stage pipeline, 1 sync/chunk, 2 CTAs/SM. (R8)
// mode 1 QKV: z==0 output pre-scaled by 0.125 (exact).
// ---------------------------------------------------------------------------
#define GA 40
#define GB 132
#define A_ST (128*GA)
#define B_ST (32*GB)
#define STAGE (A_ST + B_ST)
#define NCHUNK (HD/32)
#define NSTAGE 3
#define GEMM_SMEM (NSTAGE*STAGE*4)   // 112128 bytes

__global__ __launch_bounds__(256, 2) void gemm_tc(
    const float* __restrict__ bias0, const float* __restrict__ bias1,
    const float* __restrict__ bias2, float* __restrict__ Cout, int mode)
{
    extern __shared__ float sm[];
    const uint32_t sb = smem_u32(sm);
    const int tid = threadIdx.x;
    const int wid = tid >> 5, lane = tid & 31;
    const int wm = wid >> 2, wn = wid & 3;
    const int g = lane >> 2, t = lane & 3;
    const int z = (mode == 1) ? blockIdx.z : 0;

    const float* A = (mode == 0) ? g_ao : g_ht;
    const float* W = g_wt4 + (size_t)((mode == 0) ? 3 : z) * HD * HD;
    const float* bias = (z == 0) ? bias0 : (z == 1 ? bias1 : bias2);
    float* C = (mode == 0) ? Cout : (z == 0 ? g_q : (z == 1 ? g_k : g_v));
    const float qs = (mode == 1 && z == 0) ? 0.125f : 1.0f;

    const int m0 = blockIdx.y * 128;
    const int n0 = blockIdx.x * 128;

    float acc[4][4][4];
#pragma unroll
    for (int i = 0; i < 4; ++i)
#pragma unroll
        for (int j = 0; j < 4; ++j)
#pragma unroll
            for (int r = 0; r < 4; ++r) acc[i][j][r] = 0.0f;

#define G_LOAD(cc, st) do { \
    int k0 = (cc) * 32; \
    uint32_t abase = sb + (uint32_t)((st) * STAGE) * 4; \
    uint32_t bbase = abase + A_ST * 4; \
    _Pragma("unroll") \
    for (int it = 0; it < 4; ++it) { \
        int idx = tid + it * 256; \
        int ar = idx >> 3, ac = idx & 7; \
        cpa16(abase + (uint32_t)(ar * GA + ac * 4) * 4, \
              A + (size_t)(m0 + ar) * HD + k0 + ac * 4); \
        int br = idx >> 5, bc = idx & 31; \
        int sr = (br & ~7) | slotf(br & 7); \
        cpa16(bbase + (uint32_t)(sr * GB + bc * 4) * 4, \
              W + (size_t)(k0 + br) * HD + n0 + bc * 4); \
    } \
    CP_COMMIT(); \
} while (0)

    G_LOAD(0, 0);
    G_LOAD(1, 1);

    int st = 0;
    for (int c = 0; c < NCHUNK; ++c) {
        CP_WAIT1();
        __syncthreads();
        if (c + 2 < NCHUNK) {
            int st2 = st + 2; if (st2 >= NSTAGE) st2 -= NSTAGE;
            G_LOAD(c + 2, st2);
        }

        const float* As = sm + st * STAGE;
        const float* Bs = As + A_ST;
#pragma unroll
        for (int ks = 0; ks < 4; ++ks) {
            float2 ap[4][2];
#pragma unroll
            for (int mf = 0; mf < 4; ++mf) {
                const float* p = As + (wm * 64 + mf * 16 + g) * GA + ks * 8 + 2 * t;
                ap[mf][0] = *(const float2*)p;
                ap[mf][1] = *(const float2*)(p + 8 * GA);
            }
            float bf[4][2];
#pragma unroll
            for (int nf = 0; nf < 4; ++nf) {
                const float* p = Bs + (ks * 8 + 2 * t) * GB + wn * 32 + nf * 8 + g;
                bf[nf][0] = p[0];
                bf[nf][1] = p[GB];
            }
#pragma unroll
            for (int mf = 0; mf < 4; ++mf)
#pragma unroll
                for (int nf = 0; nf < 4; ++nf)
                    mma8(acc[mf][nf],
                         __float_as_uint(ap[mf][0].x), __float_as_uint(ap[mf][1].x),
                         __float_as_uint(ap[mf][0].y), __float_as_uint(ap[mf][1].y),
                         __float_as_uint(bf[nf][0]), __float_as_uint(bf[nf][1]));
        }
        if (++st >= NSTAGE) st = 0;
    }

    // epilogue
#pragma unroll
    for (int mf = 0; mf < 4; ++mf) {
#pragma unroll
        for (int nf = 0; nf < 4; ++nf) {
            int r0 = m0 + wm * 64 + mf * 16 + g;
            int ncol0 = n0 + wn * 32 + nf * 8 + 2 * t;
            float bb0 = bias[ncol0], bb1 = bias[ncol0 + 1];
            float v00 = acc[mf][nf][0] + bb0, v01 = acc[mf][nf][1] + bb1;
            float v10 = acc[mf][nf][2] + bb0, v11 = acc[mf][nf][3] + bb1;
            if (mode == 0) {
                *(float2*)&C[(size_t)r0 * HD + ncol0] = make_float2(v00, v01);
                *(float2*)&C[(size_t)(r0 + 8) * HD + ncol0] = make_float2(v10, v11);
            } else {
                int b = r0 >> 10, sidx = r0 & 1023;
                int hh = ncol0 >> 6, dd = ncol0 & 63;
                size_t base = ((size_t)(b * NH + hh) * SQ + sidx) * DH + dd;
                *(float2*)&C[base] = make_float2(f2tff(v00 * qs), f2tff(v01 * qs));
                *(float2*)&C[base + 8 * DH] = make_float2(f2tff(v10 * qs), f2tff(v11 * qs));
            }
        }
    }
}

// ---------------------------------------------------------------------------
// Flash attention — R9 structure; log2-domain fold (FFMA + ex2), permuted
// float4 bm loads, grid (q-tile, bh) for K/V L2 reuse.
// smem floats: K[2][64][68], V[2][64][72], Ps[128][68] (Q staging + P).
// ---------------------------------------------------------------------------
#define KSTR 68
#define VSTR 72
#define K_OFF(s)  ((s)*64*KSTR)
#define V_OFF(s)  (2*64*KSTR + (s)*64*VSTR)
#define P_OFF     (2*64*KSTR + 2*64*VSTR)
#define ATTN_FLOATS (P_OFF + 128*KSTR)
#define ATTN_SMEM (ATTN_FLOATS*4)   // 106496 bytes

__global__ __launch_bounds__(256, 2) void attn_kernel()
{
    extern __shared__ float sm[];
    const uint32_t sb = smem_u32(sm);
    const float FINF = __int_as_float(0x7f800000);
    float* Ps = sm + P_OFF;

    const int bh = blockIdx.y;
    const int b = bh / NH, hh = bh - b * NH;
    const int q0 = blockIdx.x * 128;
    const int tid = threadIdx.x;
    const int wid = tid >> 5, lane = tid & 31;
    const int g = lane >> 2, t = lane & 3;
    const int rl = wid * 16 + g;

    const float* qg = g_q + ((size_t)bh * SQ + q0) * DH;
    const float* kg = g_k + (size_t)bh * SQ * DH;
    const float* vg = g_v + (size_t)bh * SQ * DH;

    // issue chunk-0 K/V cp.async first (overlaps Q staging)
#pragma unroll
    for (int it = 0; it < 4; ++it) {
        int idx = tid + it * 256;
        int row = idx >> 4, c4 = idx & 15;
        cpa16(sb + (uint32_t)(K_OFF(0) + row * KSTR + c4 * 4) * 4,
              kg + (size_t)row * 64 + c4 * 4);
        cpa16(sb + (uint32_t)(V_OFF(0) + row * VSTR + c4 * 4) * 4,
              vg + (size_t)row * 64 + c4 * 4);
    }
    CP_COMMIT();

    // stage Q tile (128x64) into Ps, then extract fragments to registers
#pragma unroll
    for (int it = 0; it < 8; ++it) {
        int idx = tid + it * 256;
        int row = idx >> 4, c4 = idx & 15;
        *(float4*)&Ps[row * KSTR + c4 * 4] = *(const float4*)&qg[(size_t)row * 64 + c4 * 4];
    }
    __syncthreads();
    uint32_t qf[8][4];
#pragma unroll
    for (int ks = 0; ks < 8; ++ks) {
        qf[ks][0] = __float_as_uint(Ps[rl * KSTR + ks * 8 + t]);
        qf[ks][1] = __float_as_uint(Ps[(rl + 8) * KSTR + ks * 8 + t]);
        qf[ks][2] = __float_as_uint(Ps[rl * KSTR + ks * 8 + t + 4]);
        qf[ks][3] = __float_as_uint(Ps[(rl + 8) * KSTR + ks * 8 + t + 4]);
    }
    CP_WAIT0();
    __syncthreads();

    const int r0 = q0 + rl;
    const int r1 = r0 + 8;
    const float* bm_r0 = g_bm + ((size_t)bh * SQ + r0) * SQ;
    const float* bm_r1 = g_bm + ((size_t)bh * SQ + r1) * SQ;

    float l0 = 0.0f, l1 = 0.0f;
    float oacc[8][4];
#pragma unroll
    for (int nf = 0; nf < 8; ++nf)
#pragma unroll
        for (int r = 0; r < 4; ++r) oacc[nf][r] = 0.0f;

    for (int kb = 0; kb < SQ / 64; ++kb) {
        const int s = kb & 1;
        const int k0 = kb * 64;

        // ---- cp.async next K/V chunk ----
        if (kb + 1 < SQ / 64) {
            const int kn = k0 + 64;
#pragma unroll
            for (int it = 0; it < 4; ++it) {
                int idx = tid + it * 256;
                int row = idx >> 4, c4 = idx & 15;
                cpa16(sb + (uint32_t)(K_OFF(s ^ 1) + row * KSTR + c4 * 4) * 4,
                      kg + (size_t)(kn + row) * 64 + c4 * 4);
                cpa16(sb + (uint32_t)(V_OFF(s ^ 1) + row * VSTR + c4 * 4) * 4,
                      vg + (size_t)(kn + row) * 64 + c4 * 4);
            }
            CP_COMMIT();
        }

        // ---- S = Q K^T (sacc = qk * 0.125, Q pre-scaled) ----
        const float* Ksf = sm + K_OFF(s);
        float sacc[8][4];
#pragma unroll
        for (int nf = 0; nf < 8; ++nf)
#pragma unroll
            for (int r = 0; r < 4; ++r) sacc[nf][r] = 0.0f;
#pragma unroll
        for (int ks = 0; ks < 8; ++ks) {
#pragma unroll
            for (int nf = 0; nf < 8; ++nf) {
                const float* kp = Ksf + (nf * 8 + g) * KSTR + ks * 8 + t;
                mma8(sacc[nf], qf[ks][0], qf[ks][1], qf[ks][2], qf[ks][3],
                     __float_as_uint(kp[0]), __float_as_uint(kp[4]));
            }
        }

        // ---- fold: arg = sacc*log2e + bm (bm pre-scaled); ex2 ----
        float rs0 = 0.0f, rs1 = 0.0f;
#pragma unroll
        for (int v = 0; v < 4; ++v) {
            int base = k0 + t * 16 + v * 4;
            float4 U = *(const float4*)&bm_r0[base];
            float4 Wv4 = *(const float4*)&bm_r1[base];
            {
                int nf = 2 * v;
                float a0 = (U.x == FINF)   ? MASKED_ARG : fmaf(sacc[nf][0], LOG2E, U.x);
                float a1 = (U.y == FINF)   ? MASKED_ARG : fmaf(sacc[nf][1], LOG2E, U.y);
                float a2 = (Wv4.x == FINF) ? MASKED_ARG : fmaf(sacc[nf][2], LOG2E, Wv4.x);
                float a3 = (Wv4.y == FINF) ? MASKED_ARG : fmaf(sacc[nf][3], LOG2E, Wv4.y);
                sacc[nf][0] = ex2f(a0); sacc[nf][1] = ex2f(a1);
                sacc[nf][2] = ex2f(a2); sacc[nf][3] = ex2f(a3);
                rs0 += sacc[nf][0] + sacc[nf][1];
                rs1 += sacc[nf][2] + sacc[nf][3];
            }
            {
                int nf = 2 * v + 1;
                float a0 = (U.z == FINF)   ? MASKED_ARG : fmaf(sacc[nf][0], LOG2E, U.z);
                float a1 = (U.w == FINF)   ? MASKED_ARG : fmaf(sacc[nf][1], LOG2E, U.w);
                float a2 = (Wv4.z == FINF) ? MASKED_ARG : fmaf(sacc[nf][2], LOG2E, Wv4.z);
                float a3 = (Wv4.w == FINF) ? MASKED_ARG : fmaf(sacc[nf][3], LOG2E, Wv4.w);
                sacc[nf][0] = ex2f(a0); sacc[nf][1] = ex2f(a1);
                sacc[nf][2] = ex2f(a2); sacc[nf][3] = ex2f(a3);
                rs0 += sacc[nf][0] + sacc[nf][1];
                rs1 += sacc[nf][2] + sacc[nf][3];
            }
        }
        l0 += rs0;
        l1 += rs1;

        // ---- P (tf32 bits) -> smem, warp-local rows ----
#pragma unroll
        for (int nf = 0; nf < 8; ++nf) {
            int kc = nf * 8 + 2 * t;
            *(float2*)&Ps[rl * KSTR + kc] =
                make_float2(f2tff(sacc[nf][0]), f2tff(sacc[nf][1]));
            *(float2*)&Ps[(rl + 8) * KSTR + kc] =
                make_float2(f2tff(sacc[nf][2]), f2tff(sacc[nf][3]));
        }
        __syncwarp();

        // ---- O += P V ----
        const float* Vsf = sm + V_OFF(s);
#pragma unroll
        for (int ks = 0; ks < 8; ++ks) {
            const float* pp = Ps + rl * KSTR + ks * 8 + t;
            uint32_t a0 = __float_as_uint(pp[0]);
            uint32_t a1 = __float_as_uint(pp[8 * KSTR]);
            uint32_t a2 = __float_as_uint(pp[4]);
            uint32_t a3 = __float_as_uint(pp[8 * KSTR + 4]);
#pragma unroll
            for (int nf = 0; nf < 8; ++nf) {
                const float* vp = Vsf + (ks * 8 + t) * VSTR + nf * 8 + g;
                mma8(oacc[nf], a0, a1, a2, a3,
                     __float_as_uint(vp[0]), __float_as_uint(vp[4 * VSTR]));
            }
        }

        if (kb + 1 < SQ / 64) CP_WAIT0();
        __syncthreads();
    }

    // ---- final l reduction (quad) + normalize + write g_ao (kperm tf32) ----
    l0 += __shfl_xor_sync(0xffffffffu, l0, 1);
    l0 += __shfl_xor_sync(0xffffffffu, l0, 2);
    l1 += __shfl_xor_sync(0xffffffffu, l1, 1);
    l1 += __shfl_xor_sync(0xffffffffu, l1, 2);
    float inv0 = 1.0f / l0, inv1 = 1.0f / l1;
    int s0 = slotf(2 * t), s1 = slotf(2 * t + 1);
#pragma unroll
    for (int nf = 0; nf < 8; ++nf) {
        int colbase = hh * 64 + nf * 8;
        size_t b0 = (size_t)(b * SQ + r0) * HD + colbase;
        size_t b1 = (size_t)(b * SQ + r1) * HD + colbase;
        g_ao[b0 + s0] = f2tff(oacc[nf][0] * inv0);
        g_ao[b0 + s1] = f2tff(oacc[nf][1] * inv0);
        g_ao[b1 + s0] = f2tff(oacc[nf][2] * inv1);
        g_ao[b1 + s1] = f2tff(oacc[nf][3] * inv1);
    }
}

// ---------------------------------------------------------------------------
extern "C" void kernel_launch(void* const* d_in, const int* in_sizes, int n_in,
                              void* d_out, int out_size)
{
    const float* h  = (const float*)d_in[0];
    const float* ab = (const float*)d_in[1];
    const int*   mk = (const int*)d_in[2];
    const float* Wq = (const float*)d_in[3];
    const float* bq = (const float*)d_in[4];
    const float* Wk = (const float*)d_in[5];
    const float* bk = (const float*)d_in[6];
    const float* Wv = (const float*)d_in[7];
    const float* bv = (const float*)d_in[8];
    const float* Wo = (const float*)d_in[9];
    const float* bo = (const float*)d_in[10];
    float* out = (float*)d_out;

    cudaFuncSetAttribute(gemm_tc,
                         cudaFuncAttributeMaxDynamicSharedMemorySize, GEMM_SMEM);
    cudaFuncSetAttribute(attn_kernel,
                         cudaFuncAttributeMaxDynamicSharedMemorySize, ATTN_SMEM);

    prep<<<(MROWS*HD + 255) / 256, 256>>>(h, Wq, Wk, Wv, Wo);
    repack<<<dim3(SQ, NB), 256>>>(ab, mk);
    gemm_tc<<<dim3(HD / 128, MROWS / 128, 3), 256, GEMM_SMEM>>>(
        bq, bk, bv, nullptr, 1);
    attn_kernel<<<dim3(SQ / 128, BHCOUNT), 256, ATTN_SMEM>>>();
    gemm_tc<<<dim3(HD / 128, MROWS / 128, 1), 256, GEMM_SMEM>>>(
        bo, bo, bo, out, 0);
}

// round 11
// speedup vs baseline: 1.5350x; 1.0071x over previous
#include <cuda_runtime.h>
#include <cstdint>

// Problem constants
#define SQ 1024
#define HD 768
#define NH 12
#define DH 64
#define NB 8
#define BHCOUNT (NB*NH)   // 96
#define MROWS (NB*SQ)     // 8192

// Scratch (device globals; tf32 bit patterns stored as float)
__device__ float g_q[BHCOUNT*SQ*DH];    // natural head-major tf32, pre-scaled by 0.125
__device__ float g_k[BHCOUNT*SQ*DH];    // natural head-major tf32
__device__ float g_v[BHCOUNT*SQ*DH];    // natural head-major tf32
__device__ float g_ao[MROWS*HD];        // kperm'd tf32 (for O-proj A-path)
__device__ float g_ht[MROWS*HD];        // kperm'd tf32 input h
__device__ float g_wt4[4*HD*HD];        // tf32 weights (natural)
__device__ float g_bm[(size_t)BHCOUNT*SQ*SQ];  // (bias-16)*log2e, FINF if masked; col-permuted

#define LOG2E 1.4426950408889634f
#define MASKED_ARG (-23.08312065422341f)   // (1e-14 - 16) * log2e

// ---------------------------------------------------------------------------
// helpers
// ---------------------------------------------------------------------------
__device__ __forceinline__ uint32_t f2tf(float x) {
    uint32_t r;
    asm("cvt.rna.tf32.f32 %0, %1;" : "=r"(r) : "f"(x));
    return r;
}
__device__ __forceinline__ float f2tff(float x) { return __uint_as_float(f2tf(x)); }
__device__ __forceinline__ float ex2f(float x) {
    float r;
    asm("ex2.approx.ftz.f32 %0, %1;" : "=f"(r) : "f"(x));
    return r;
}
__device__ __forceinline__ int slotf(int c) { return 2*(c&3) + ((c&4)>>2); }

__device__ __forceinline__ void mma8(float* c,
                                     uint32_t a0, uint32_t a1, uint32_t a2, uint32_t a3,
                                     uint32_t b0, uint32_t b1) {
    asm volatile(
        "mma.sync.aligned.m16n8k8.row.col.f32.tf32.tf32.f32 "
        "{%0,%1,%2,%3}, {%4,%5,%6,%7}, {%8,%9}, {%0,%1,%2,%3};"
        : "+f"(c[0]), "+f"(c[1]), "+f"(c[2]), "+f"(c[3])
        : "r"(a0), "r"(a1), "r"(a2), "r"(a3), "r"(b0), "r"(b1));
}

__device__ __forceinline__ uint32_t smem_u32(const void* p) {
    uint32_t a;
    asm("{ .reg .u64 t; cvta.to.shared.u64 t, %1; cvt.u32.u64 %0, t; }"
        : "=r"(a) : "l"(p));
    return a;
}
__device__ __forceinline__ void cpa16(uint32_t dst, const void* src) {
    asm volatile("cp.async.cg.shared.global [%0], [%1], 16;" :: "r"(dst), "l"(src));
}
#define CP_COMMIT() asm volatile("cp.async.commit_group;" ::: "memory")
#define CP_WAIT0()  asm volatile("cp.async.wait_group 0;" ::: "memory")
#define CP_WAIT1()  asm volatile("cp.async.wait_group 1;" ::: "memory")

// ---------------------------------------------------------------------------
// prep: g_ht = kperm'd tf32(h); g_wt4 = tf32(weights), natural
// ---------------------------------------------------------------------------
__global__ void prep(const float* __restrict__ h,
                     const float* __restrict__ wq, const float* __restrict__ wk,
                     const float* __restrict__ wv, const float* __restrict__ wo)
{
    int i = blockIdx.x * 256 + threadIdx.x;
    if (i < MROWS*HD) {
        int k = i & 7;
        g_ht[i - k + slotf(k)] = f2tff(h[i]);
    }
    if (i < 4*HD*HD) {
        int z = i / (HD*HD), r = i - z*(HD*HD);
        const float* w = (z == 0) ? wq : (z == 1 ? wk : (z == 2 ? wv : wo));
        g_wt4[i] = f2tff(w[r]);
    }
}

// ---------------------------------------------------------------------------
// GEMM tile body (tf32 mma.sync, cp.async 3-stage). Shared by fused QKV and
// the O-projection kernel.
// ---------------------------------------------------------------------------
#define GA 40
#define GB 132
#define A_ST (128*GA)
#define B_ST (32*GB)
#define STAGE (A_ST + B_ST)
#define NCHUNK (HD/32)
#define NSTAGE 3
#define GEMM_SMEM (NSTAGE*STAGE*4)   // 112128 bytes

__device__ __forceinline__ void gemm_tile(
    float* sm, int bx, int by, int z, int mode,
    const float* __restrict__ bias, float* __restrict__ Cout)
{
    const uint32_t sb = smem_u32(sm);
    const int tid = threadIdx.x;
    const int lane = tid & 31;
    const int wm = (tid >> 5) >> 2, wn = (tid >> 5) & 3;
    const int g = lane >> 2, t = lane & 3;

    const float* A = (mode == 0) ? g_ao : g_ht;
    const float* W = g_wt4 + (size_t)((mode == 0) ? 3 : z) * HD * HD;
    float* C = (mode == 0) ? Cout : (z == 0 ? g_q : (z == 1 ? g_k : g_v));
    const float qs = (mode == 1 && z == 0) ? 0.125f : 1.0f;

    const int m0 = by * 128;
    const int n0 = bx * 128;

    float acc[4][4][4];
#pragma unroll
    for (int i = 0; i < 4; ++i)
#pragma unroll
        for (int j = 0; j < 4; ++j)
#pragma unroll
            for (int r = 0; r < 4; ++r) acc[i][j][r] = 0.0f;

#define G_LOAD(cc, st) do { \
    int k0 = (cc) * 32; \
    uint32_t abase = sb + (uint32_t)((st) * STAGE) * 4; \
    uint32_t bbase = abase + A_ST * 4; \
    _Pragma("unroll") \
    for (int it = 0; it < 4; ++it) { \
        int idx = tid + it * 256; \
        int ar = idx >> 3, ac = idx & 7; \
        cpa16(abase + (uint32_t)(ar * GA + ac * 4) * 4, \
              A + (size_t)(m0 + ar) * HD + k0 + ac * 4); \
        int br = idx >> 5, bc = idx & 31; \
        int sr = (br & ~7) | slotf(br & 7); \
        cpa16(bbase + (uint32_t)(sr * GB + bc * 4) * 4, \
              W + (size_t)(k0 + br) * HD + n0 + bc * 4); \
    } \
    CP_COMMIT(); \
} while (0)

    G_LOAD(0, 0);
    G_LOAD(1, 1);

    int st = 0;
    for (int c = 0; c < NCHUNK; ++c) {
        CP_WAIT1();
        __syncthreads();
        if (c + 2 < NCHUNK) {
            int st2 = st + 2; if (st2 >= NSTAGE) st2 -= NSTAGE;
            G_LOAD(c + 2, st2);
        }

        const float* As = sm + st * STAGE;
        const float* Bs = As + A_ST;
#pragma unroll
        for (int ks = 0; ks < 4; ++ks) {
            float2 ap[4][2];
#pragma unroll
            for (int mf = 0; mf < 4; ++mf) {
                const float* p = As + (wm * 64 + mf * 16 + g) * GA + ks * 8 + 2 * t;
                ap[mf][0] = *(const float2*)p;
                ap[mf][1] = *(const float2*)(p + 8 * GA);
            }
            float bf[4][2];
#pragma unroll
            for (int nf = 0; nf < 4; ++nf) {
                const float* p = Bs + (ks * 8 + 2 * t) * GB + wn * 32 + nf * 8 + g;
                bf[nf][0] = p[0];
                bf[nf][1] = p[GB];
            }
#pragma unroll
            for (int mf = 0; mf < 4; ++mf)
#pragma unroll
                for (int nf = 0; nf < 4; ++nf)
                    mma8(acc[mf][nf],
                         __float_as_uint(ap[mf][0].x), __float_as_uint(ap[mf][1].x),
                         __float_as_uint(ap[mf][0].y), __float_as_uint(ap[mf][1].y),
                         __float_as_uint(bf[nf][0]), __float_as_uint(bf[nf][1]));
        }
        if (++st >= NSTAGE) st = 0;
    }

    // epilogue
#pragma unroll
    for (int mf = 0; mf < 4; ++mf) {
#pragma unroll
        for (int nf = 0; nf < 4; ++nf) {
            int r0 = m0 + wm * 64 + mf * 16 + g;
            int ncol0 = n0 + wn * 32 + nf * 8 + 2 * t;
            float bb0 = bias[ncol0], bb1 = bias[ncol0 + 1];
            float v00 = acc[mf][nf][0] + bb0, v01 = acc[mf][nf][1] + bb1;
            float v10 = acc[mf][nf][2] + bb0, v11 = acc[mf][nf][3] + bb1;
            if (mode == 0) {
                *(float2*)&C[(size_t)r0 * HD + ncol0] = make_float2(v00, v01);
                *(float2*)&C[(size_t)(r0 + 8) * HD + ncol0] = make_float2(v10, v11);
            } else {
                int b = r0 >> 10, sidx = r0 & 1023;
                int hh = ncol0 >> 6, dd = ncol0 & 63;
                size_t base = ((size_t)(b * NH + hh) * SQ + sidx) * DH + dd;
                *(float2*)&C[base] = make_float2(f2tff(v00 * qs), f2tff(v01 * qs));
                *(float2*)&C[base + 8 * DH] = make_float2(f2tff(v10 * qs), f2tff(v11 * qs));
            }
        }
    }
}

// ---------------------------------------------------------------------------
// repack block body: g_bm[(b*NH+h)][q][perm(k)] = mask ? INF : (bias-16)*log2e
// Uses the fused kernel's dynamic smem (52 KB of it).
// ---------------------------------------------------------------------------
__device__ __forceinline__ void repack_block(
    float* sm, int q, int b,
    const float* __restrict__ bias, const int* __restrict__ mask)
{
    float* sbias = sm;                       // SQ*NH floats (48 KB)
    int*   smask = (int*)(sm + SQ * NH);     // SQ ints (4 KB)
    const int tid = threadIdx.x;
    const float FINF = __int_as_float(0x7f800000);

    const float* bsrc = bias + ((size_t)(b * SQ + q) * SQ) * NH;
#pragma unroll
    for (int it = 0; it < 12; ++it) {
        int i4 = (tid + it * 256) * 4;
        *(float4*)&sbias[i4] = *(const float4*)&bsrc[i4];
    }
    {
        const int* msrc = mask + (size_t)(b * SQ + q) * SQ;
        int i4 = tid * 4;
        *(int4*)&smask[i4] = *(const int4*)&msrc[i4];
    }
    __syncthreads();

#pragma unroll
    for (int h = 0; h < NH; ++h) {
        float* dst = g_bm + (((size_t)(b * NH + h) * SQ + q) * SQ);
        int p0 = tid * 4;
        float o[4];
#pragma unroll
        for (int e = 0; e < 4; ++e) {
            int p = p0 + e;
            int w = p & 63, t = w >> 4, idx = w & 15;
            int k = (p & ~63) + (idx >> 1) * 8 + 2 * t + (idx & 1);
            o[e] = smask[k] ? FINF : (sbias[k * NH + h] - 16.0f) * LOG2E;
        }
        *(float4*)&dst[p0] = make_float4(o[0], o[1], o[2], o[3]);
    }
}

// ---------------------------------------------------------------------------
// Fused dispatch: 9344 blocks. gid % 8 == 0 (gid < 9216) -> QKV GEMM tile
// (1152 of them); all others -> repack blocks (8192). Interleaving keeps both
// resident per SM so repack's DRAM streaming hides under GEMM tensor work.
// ---------------------------------------------------------------------------
#define FUSED_BLOCKS (9216 + 128)   // 9344

__global__ __launch_bounds__(256, 2) void fused_qkv_repack(
    const float* __restrict__ bq, const float* __restrict__ bk,
    const float* __restrict__ bv,
    const float* __restrict__ bias, const int* __restrict__ mask)
{
    extern __shared__ float sm[];
    const int gid = blockIdx.x;
    if (((gid & 7) == 0) && (gid < 9216)) {
        int gb = gid >> 3;               // 0..1151
        int z = gb / 384;
        int rem = gb - z * 384;
        int by = rem / 6, bx = rem - by * 6;
        const float* bias_z = (z == 0) ? bq : (z == 1 ? bk : bv);
        gemm_tile(sm, bx, by, z, 1, bias_z, nullptr);
    } else {
        int rix = (gid < 9216) ? (gid - (gid >> 3) - 1) : (gid - 1152);
        int q = rix & 1023, b = rix >> 10;
        repack_block(sm, q, b, bias, mask);
    }
}

// ---------------------------------------------------------------------------
// O-projection GEMM kernel (mode 0 wrapper over gemm_tile)
// ---------------------------------------------------------------------------
__global__ __launch_bounds__(256, 2) void gemm_o(
    const float* __restrict__ bo, float* __restrict__ Cout)
{
    extern __shared__ float sm[];
    gemm_tile(sm, blockIdx.x, blockIdx.y, 0, 0, bo, Cout);
}

// ---------------------------------------------------------------------------
// Flash attention — unchanged R10 winner.
// smem floats: K[2][64][68], V[2][64][72], Ps[128][68] (Q staging + P).
// ---------------------------------------------------------------------------
#define KSTR 68
#define VSTR 72
#define K_OFF(s)  ((s)*64*KSTR)
#define V_OFF(s)  (2*64*KSTR + (s)*64*VSTR)
#define P_OFF     (2*64*KSTR + 2*64*VSTR)
#define ATTN_FLOATS (P_OFF + 128*KSTR)
#define ATTN_SMEM (ATTN_FLOATS*4)   // 106496 bytes

__global__ __launch_bounds__(256, 2) void attn_kernel()
{
    extern __shared__ float sm[];
    const uint32_t sb = smem_u32(sm);
    const float FINF = __int_as_float(0x7f800000);
    float* Ps = sm + P_OFF;

    const int bh = blockIdx.y;
    const int b = bh / NH, hh = bh - b * NH;
    const int q0 = blockIdx.x * 128;
    const int tid = threadIdx.x;
    const int wid = tid >> 5, lane = tid & 31;
    const int g = lane >> 2, t = lane & 3;
    const int rl = wid * 16 + g;

    const float* qg = g_q + ((size_t)bh * SQ + q0) * DH;
    const float* kg = g_k + (size_t)bh * SQ * DH;
    const float* vg = g_v + (size_t)bh * SQ * DH;

    // issue chunk-0 K/V cp.async first (overlaps Q staging)
#pragma unroll
    for (int it = 0; it < 4; ++it) {
        int idx = tid + it * 256;
        int row = idx >> 4, c4 = idx & 15;
        cpa16(sb + (uint32_t)(K_OFF(0) + row * KSTR + c4 * 4) * 4,
              kg + (size_t)row * 64 + c4 * 4);
        cpa16(sb + (uint32_t)(V_OFF(0) + row * VSTR + c4 * 4) * 4,
              vg + (size_t)row * 64 + c4 * 4);
    }
    CP_COMMIT();

    // stage Q tile (128x64) into Ps, then extract fragments to registers
#pragma unroll
    for (int it = 0; it < 8; ++it) {
        int idx = tid + it * 256;
        int row = idx >> 4, c4 = idx & 15;
        *(float4*)&Ps[row * KSTR + c4 * 4] = *(const float4*)&qg[(size_t)row * 64 + c4 * 4];
    }
    __syncthreads();
    uint32_t qf[8][4];
#pragma unroll
    for (int ks = 0; ks < 8; ++ks) {
        qf[ks][0] = __float_as_uint(Ps[rl * KSTR + ks * 8 + t]);
        qf[ks][1] = __float_as_uint(Ps[(rl + 8) * KSTR + ks * 8 + t]);
        qf[ks][2] = __float_as_uint(Ps[rl * KSTR + ks * 8 + t + 4]);
        qf[ks][3] = __float_as_uint(Ps[(rl + 8) * KSTR + ks * 8 + t + 4]);
    }
    CP_WAIT0();
    __syncthreads();

    const int r0 = q0 + rl;
    const int r1 = r0 + 8;
    const float* bm_r0 = g_bm + ((size_t)bh * SQ + r0) * SQ;
    const float* bm_r1 = g_bm + ((size_t)bh * SQ + r1) * SQ;

    float l0 = 0.0f, l1 = 0.0f;
    float oacc[8][4];
#pragma unroll
    for (int nf = 0; nf < 8; ++nf)
#pragma unroll
        for (int r = 0; r < 4; ++r) oacc[nf][r] = 0.0f;

    for (int kb = 0; kb < SQ / 64; ++kb) {
        const int s = kb & 1;
        const int k0 = kb * 64;

        // ---- cp.async next K/V chunk ----
        if (kb + 1 < SQ / 64) {
            const int kn = k0 + 64;
#pragma unroll
            for (int it = 0; it < 4; ++it) {
                int idx = tid + it * 256;
                int row = idx >> 4, c4 = idx & 15;
                cpa16(sb + (uint32_t)(K_OFF(s ^ 1) + row * KSTR + c4 * 4) * 4,
                      kg + (size_t)(kn + row) * 64 + c4 * 4);
                cpa16(sb + (uint32_t)(V_OFF(s ^ 1) + row * VSTR + c4 * 4) * 4,
                      vg + (size_t)(kn + row) * 64 + c4 * 4);
            }
            CP_COMMIT();
        }

        // ---- S = Q K^T (sacc = qk * 0.125, Q pre-scaled) ----
        const float* Ksf = sm + K_OFF(s);
        float sacc[8][4];
#pragma unroll
        for (int nf = 0; nf < 8; ++nf)
#pragma unroll
            for (int r = 0; r < 4; ++r) sacc[nf][r] = 0.0f;
#pragma unroll
        for (int ks = 0; ks < 8; ++ks) {
#pragma unroll
            for (int nf = 0; nf < 8; ++nf) {
                const float* kp = Ksf + (nf * 8 + g) * KSTR + ks * 8 + t;
                mma8(sacc[nf], qf[ks][0], qf[ks][1], qf[ks][2], qf[ks][3],
                     __float_as_uint(kp[0]), __float_as_uint(kp[4]));
            }
        }

        // ---- fold: arg = sacc*log2e + bm (bm pre-scaled); ex2 ----
        float rs0 = 0.0f, rs1 = 0.0f;
#pragma unroll
        for (int v = 0; v < 4; ++v) {
            int base = k0 + t * 16 + v * 4;
            float4 U = *(const float4*)&bm_r0[base];
            float4 Wv4 = *(const float4*)&bm_r1[base];
            {
                int nf = 2 * v;
                float a0 = (U.x == FINF)   ? MASKED_ARG : fmaf(sacc[nf][0], LOG2E, U.x);
                float a1 = (U.y == FINF)   ? MASKED_ARG : fmaf(sacc[nf][1], LOG2E, U.y);
                float a2 = (Wv4.x == FINF) ? MASKED_ARG : fmaf(sacc[nf][2], LOG2E, Wv4.x);
                float a3 = (Wv4.y == FINF) ? MASKED_ARG : fmaf(sacc[nf][3], LOG2E, Wv4.y);
                sacc[nf][0] = ex2f(a0); sacc[nf][1] = ex2f(a1);
                sacc[nf][2] = ex2f(a2); sacc[nf][3] = ex2f(a3);
                rs0 += sacc[nf][0] + sacc[nf][1];
                rs1 += sacc[nf][2] + sacc[nf][3];
            }
            {
                int nf = 2 * v + 1;
                float a0 = (U.z == FINF)   ? MASKED_ARG : fmaf(sacc[nf][0], LOG2E, U.z);
                float a1 = (U.w == FINF)   ? MASKED_ARG : fmaf(sacc[nf][1], LOG2E, U.w);
                float a2 = (Wv4.z == FINF) ? MASKED_ARG : fmaf(sacc[nf][2], LOG2E, Wv4.z);
                float a3 = (Wv4.w == FINF) ? MASKED_ARG : fmaf(sacc[nf][3], LOG2E, Wv4.w);
                sacc[nf][0] = ex2f(a0); sacc[nf][1] = ex2f(a1);
                sacc[nf][2] = ex2f(a2); sacc[nf][3] = ex2f(a3);
                rs0 += sacc[nf][0] + sacc[nf][1];
                rs1 += sacc[nf][2] + sacc[nf][3];
            }
        }
        l0 += rs0;
        l1 += rs1;

        // ---- P (tf32 bits) -> smem, warp-local rows ----
#pragma unroll
        for (int nf = 0; nf < 8; ++nf) {
            int kc = nf * 8 + 2 * t;
            *(float2*)&Ps[rl * KSTR + kc] =
                make_float2(f2tff(sacc[nf][0]), f2tff(sacc[nf][1]));
            *(float2*)&Ps[(rl + 8) * KSTR + kc] =
                make_float2(f2tff(sacc[nf][2]), f2tff(sacc[nf][3]));
        }
        __syncwarp();

        // ---- O += P V ----
        const float* Vsf = sm + V_OFF(s);
#pragma unroll
        for (int ks = 0; ks < 8; ++ks) {
            const float* pp = Ps + rl * KSTR + ks * 8 + t;
            uint32_t a0 = __float_as_uint(pp[0]);
            uint32_t a1 = __float_as_uint(pp[8 * KSTR]);
            uint32_t a2 = __float_as_uint(pp[4]);
            uint32_t a3 = __float_as_uint(pp[8 * KSTR + 4]);
#pragma unroll
            for (int nf = 0; nf < 8; ++nf) {
                const float* vp = Vsf + (ks * 8 + t) * VSTR + nf * 8 + g;
                mma8(oacc[nf], a0, a1, a2, a3,
                     __float_as_uint(vp[0]), __float_as_uint(vp[4 * VSTR]));
            }
        }

        if (kb + 1 < SQ / 64) CP_WAIT0();
        __syncthreads();
    }

    // ---- final l reduction (quad) + normalize + write g_ao (kperm tf32) ----
    l0 += __shfl_xor_sync(0xffffffffu, l0, 1);
    l0 += __shfl_xor_sync(0xffffffffu, l0, 2);
    l1 += __shfl_xor_sync(0xffffffffu, l1, 1);
    l1 += __shfl_xor_sync(0xffffffffu, l1, 2);
    float inv0 = 1.0f / l0, inv1 = 1.0f / l1;
    int s0 = slotf(2 * t), s1 = slotf(2 * t + 1);
#pragma unroll
    for (int nf = 0; nf < 8; ++nf) {
        int colbase = hh * 64 + nf * 8;
        size_t b0 = (size_t)(b * SQ + r0) * HD + colbase;
        size_t b1 = (size_t)(b * SQ + r1) * HD + colbase;
        g_ao[b0 + s0] = f2tff(oacc[nf][0] * inv0);
        g_ao[b0 + s1] = f2tff(oacc[nf][1] * inv0);
        g_ao[b1 + s0] = f2tff(oacc[nf][2] * inv1);
        g_ao[b1 + s1] = f2tff(oacc[nf][3] * inv1);
    }
}

// ---------------------------------------------------------------------------
extern "C" void kernel_launch(void* const* d_in, const int* in_sizes, int n_in,
                              void* d_out, int out_size)
{
    const float* h  = (const float*)d_in[0];
    const float* ab = (const float*)d_in[1];
    const int*   mk = (const int*)d_in[2];
    const float* Wq = (const float*)d_in[3];
    const float* bq = (const float*)d_in[4];
    const float* Wk = (const float*)d_in[5];
    const float* bk = (const float*)d_in[6];
    const float* Wv = (const float*)d_in[7];
    const float* bv = (const float*)d_in[8];
    const float* Wo = (const float*)d_in[9];
    const float* bo = (const float*)d_in[10];
    float* out = (float*)d_out;

    cudaFuncSetAttribute(fused_qkv_repack,
                         cudaFuncAttributeMaxDynamicSharedMemorySize, GEMM_SMEM);
    cudaFuncSetAttribute(gemm_o,
                         cudaFuncAttributeMaxDynamicSharedMemorySize, GEMM_SMEM);
    cudaFuncSetAttribute(attn_kernel,
                         cudaFuncAttributeMaxDynamicSharedMemorySize, ATTN_SMEM);

    prep<<<(MROWS*HD + 255) / 256, 256>>>(h, Wq, Wk, Wv, Wo);
    fused_qkv_repack<<<FUSED_BLOCKS, 256, GEMM_SMEM>>>(bq, bk, bv, ab, mk);
    attn_kernel<<<dim3(SQ / 128, BHCOUNT), 256, ATTN_SMEM>>>();
    gemm_o<<<dim3(HD / 128, MROWS / 128), 256, GEMM_SMEM>>>(bo, out);
}